// round 14
// baseline (speedup 1.0000x reference)
#include <cuda_runtime.h>
#include <cstdint>
#include <cstddef>

#define BB 256
#define SS 64
#define RR 256
#define VV 2000
#define CC 10
#define KKC 6
#define DD 256
#define MAXRC 48
#define MNCAP 16
#define HW_PITCH 128

typedef unsigned long long ull;

// ---------------- scratch (device globals) ----------------
__device__ float g_Q[RR * DD];
__device__ float g_Kx[BB * SS * DD];
__device__ float g_Vx[BB * SS * DD];
__device__ float g_ctx[(size_t)BB * RR * DD];
__device__ int g_adjflag;
__device__ unsigned int g_adjbits[RR * 8];
__device__ int g_nbr_cnt[RR];
__device__ int g_nbr[RR * RR];
__device__ int g_memb_cnt[CC];
__device__ int g_memb_idx[CC * MAXRC];
__device__ int g_memb_inv[CC * RR];
__device__ int g_mn_cnt[CC * RR];
__device__ unsigned char g_mn_jc8[CC * RR * MNCAP];
__device__ float g_hW1c[(size_t)CC * BB * MAXRC * 128];
__device__ float g_a2dp[CC * 128];
__device__ float g_a2sp[CC * 128];
__device__ float g_Wf[CC * DD * 128];    // Wo @ W1[c]
__device__ float g_bo1[CC * 128];        // bo @ W1[c]

__device__ __forceinline__ float lrelu02(float x) { return x > 0.f ? x : 0.2f * x; }
__device__ __forceinline__ ull pkdup(float x) { ull r; asm("mov.b64 %0,{%1,%1};" : "=l"(r) : "f"(x)); return r; }
__device__ __forceinline__ void fma2(ull& d, ull a, ull b) { asm("fma.rn.f32x2 %0,%1,%2,%0;" : "+l"(d) : "l"(a), "l"(b)); }
__device__ __forceinline__ void unpk(ull v, float& lo, float& hi) { asm("mov.b64 {%0,%1},%2;" : "=f"(lo), "=f"(hi) : "l"(v)); }

// ---------------- adj dtype sniff ----------------
__global__ void k_sniff(const void* __restrict__ adjraw) {
    __shared__ int cntA, cntB;
    int tid = threadIdx.x;
    if (tid == 0) { cntA = 0; cntB = 0; }
    __syncthreads();
    const uint4* p = (const uint4*)adjraw;
    int a = 0, b = 0;
    for (int i = tid; i < RR * RR / 16; i += 256) {
        uint4 v = p[i];
        unsigned int w[4] = {v.x, v.y, v.z, v.w};
#pragma unroll
        for (int q = 0; q < 4; q++) {
            a += ((w[q] & 0xFFu) != 0);
            b += (((w[q] >> 8) & 0xFFu) != 0) + (((w[q] >> 16) & 0xFFu) != 0) + ((w[q] >> 24) != 0);
        }
    }
    atomicAdd(&cntA, a);
    atomicAdd(&cntB, b);
    __syncthreads();
    if (tid == 0) {
        if (cntB == 0) g_adjflag = 0;
        else if (cntA == 0) g_adjflag = 1;
        else g_adjflag = 2;
    }
}

// ---------------- adjacency CSR + bitmask via ballot ----------------
__global__ void k_csr(const void* __restrict__ adjraw) {
    __shared__ unsigned int words[8];
    __shared__ int base[8];
    const int r = blockIdx.x, tid = threadIdx.x;
    const int warp = tid >> 5, lane = tid & 31;
    const int flag = g_adjflag;
    bool nz;
    if (flag == 0) nz = ((const int*)adjraw)[r * RR + tid] != 0;
    else if (flag == 1) nz = ((const float*)adjraw)[r * RR + tid] != 0.f;
    else nz = ((const unsigned char*)adjraw)[r * RR + tid] != 0;
    unsigned int ball = __ballot_sync(0xffffffffu, nz);
    if (lane == 0) words[warp] = ball;
    __syncthreads();
    if (tid == 0) {
        int s = 0;
#pragma unroll
        for (int w = 0; w < 8; w++) { base[w] = s; s += __popc(words[w]); }
        g_nbr_cnt[r] = s;
    }
    if (tid < 8) g_adjbits[r * 8 + tid] = words[tid];
    __syncthreads();
    if (nz) {
        int pos = base[warp] + __popc(ball & ((1u << lane) - 1));
        g_nbr[r * RR + pos] = tid;
    }
}

// ---------------- per-class membership + u8 member-neighbor lists ----------------
__global__ void k_memb(const int* __restrict__ mask) {
    __shared__ unsigned int words[8];
    __shared__ int base[8];
    __shared__ int invsm[RR];
    const int c = blockIdx.x, tid = threadIdx.x;
    const int warp = tid >> 5, lane = tid & 31;
    bool mem = mask[c * RR + tid] != 0;
    unsigned int ball = __ballot_sync(0xffffffffu, mem);
    if (lane == 0) words[warp] = ball;
    __syncthreads();
    if (tid == 0) {
        int s = 0;
#pragma unroll
        for (int w = 0; w < 8; w++) { base[w] = s; s += __popc(words[w]); }
        g_memb_cnt[c] = s < MAXRC ? s : MAXRC;
    }
    __syncthreads();
    int inv = -1;
    if (mem) {
        int pos = base[warp] + __popc(ball & ((1u << lane) - 1));
        if (pos < MAXRC) { inv = pos; g_memb_idx[c * MAXRC + pos] = tid; }
    }
    invsm[tid] = inv;
    g_memb_inv[c * RR + tid] = inv;
    __syncthreads();
    int i = tid;
    int deg = g_nbr_cnt[i];
    const int* nb = g_nbr + i * RR;
    int mc = 0;
    for (int m = 0; m < deg; m++) {
        int j = nb[m];
        int jc = invsm[j];
        if (jc >= 0 && mc < MNCAP) {
            g_mn_jc8[(c * RR + i) * MNCAP + mc] = (unsigned char)jc;
            mc++;
        }
    }
    for (int m = mc; m < MNCAP; m++) g_mn_jc8[(c * RR + i) * MNCAP + m] = 0;
    g_mn_cnt[c * RR + i] = mc;
}

// ---------------- rule embedding fused with scaled Q projection ----------------
__global__ void k_rule(const float* __restrict__ basic, const float* __restrict__ crucial,
                       const float* __restrict__ Wtb, const float* __restrict__ btb,
                       const float* __restrict__ Wtk, const float* __restrict__ btk,
                       const float* __restrict__ Wq, const float* __restrict__ bq) {
    __shared__ int nzb[64], nzc[64];
    __shared__ float vb[64], vc[64];
    __shared__ int cb[256], cc2[256];
    __shared__ int totb, totc;
    __shared__ float rulesm[256];
    int r = blockIdx.x, tid = threadIdx.x;
    const float* br = basic + (size_t)r * VV;
    const float* cr = crucial + (size_t)r * VV;
    int nb = 0, nc = 0;
    int v0 = tid * 8;
#pragma unroll
    for (int t = 0; t < 8; t++) {
        int v = v0 + t;
        if (v < VV) { if (br[v] != 0.f) nb++; if (cr[v] != 0.f) nc++; }
    }
    cb[tid] = nb; cc2[tid] = nc;
    __syncthreads();
    if (tid == 0) {
        int s = 0;
        for (int i = 0; i < 256; i++) { int t = cb[i]; cb[i] = s; s += t; }
        totb = s < 64 ? s : 64;
        s = 0;
        for (int i = 0; i < 256; i++) { int t = cc2[i]; cc2[i] = s; s += t; }
        totc = s < 64 ? s : 64;
    }
    __syncthreads();
    {
        int ob = cb[tid], oc = cc2[tid];
#pragma unroll
        for (int t = 0; t < 8; t++) {
            int v = v0 + t;
            if (v < VV) {
                if (br[v] != 0.f && ob < 64) { nzb[ob] = v; vb[ob] = br[v]; ob++; }
                if (cr[v] != 0.f && oc < 64) { nzc[oc] = v; vc[oc] = cr[v]; oc++; }
            }
        }
    }
    __syncthreads();
    int d = tid;
    float acc = btb[d] + btk[d];
    int tb = totb, tc = totc;
    for (int i = 0; i < tb; i++) acc += vb[i] * Wtb[(size_t)nzb[i] * DD + d];
    for (int i = 0; i < tc; i++) acc += vc[i] * Wtk[(size_t)nzc[i] * DD + d];
    rulesm[d] = acc;
    __syncthreads();
    float q = bq[d];
#pragma unroll 4
    for (int e = 0; e < 256; e++) q += rulesm[e] * Wq[(size_t)e * DD + d];
    g_Q[(size_t)r * DD + d] = q * 0.125f;
}

// ---------------- f32x2 GEMM, N=K=256 ----------------
__global__ void __launch_bounds__(256, 2)
k_gemm256(const float* __restrict__ A, const float* __restrict__ W,
          const float* __restrict__ bias, float* __restrict__ C) {
    __shared__ float As[32][130];
    __shared__ float Bs[32][128];
    __shared__ float bsm[128];
    const int tid = threadIdx.x;
    const int row0 = blockIdx.y * 128, col0 = blockIdx.x * 128;
    const int trow = tid >> 4, tcol = tid & 15;
    if (tid < 128) bsm[tid] = bias[col0 + tid];
    ull acc[4][8];
#pragma unroll
    for (int p = 0; p < 4; p++)
#pragma unroll
        for (int j = 0; j < 8; j++) acc[p][j] = 0ull;
    for (int k0 = 0; k0 < 256; k0 += 32) {
#pragma unroll
        for (int t = 0; t < 4; t++) {
            int idx = (tid + t * 256) * 4;
            int r = idx >> 5, kk = idx & 31;
            float4 v = *(const float4*)(A + (size_t)(row0 + r) * 256 + k0 + kk);
            As[kk][r] = v.x; As[kk + 1][r] = v.y; As[kk + 2][r] = v.z; As[kk + 3][r] = v.w;
        }
#pragma unroll
        for (int t = 0; t < 4; t++) {
            int idx = (tid + t * 256) * 4;
            int rk = idx >> 7, cc = idx & 127;
            *(float4*)&Bs[rk][cc] = *(const float4*)(W + (size_t)(k0 + rk) * 256 + col0 + cc);
        }
        __syncthreads();
#pragma unroll
        for (int k = 0; k < 32; k++) {
            ull a2[4], b2[8];
#pragma unroll
            for (int p = 0; p < 4; p++) a2[p] = *(const ull*)&As[k][trow * 8 + 2 * p];
#pragma unroll
            for (int j = 0; j < 8; j++) b2[j] = pkdup(Bs[k][tcol + 16 * j]);
#pragma unroll
            for (int p = 0; p < 4; p++)
#pragma unroll
                for (int j = 0; j < 8; j++) fma2(acc[p][j], a2[p], b2[j]);
        }
        __syncthreads();
    }
#pragma unroll
    for (int p = 0; p < 4; p++) {
        float* C0 = C + (size_t)(row0 + trow * 8 + 2 * p) * 256 + col0;
        float* C1 = C0 + 256;
#pragma unroll
        for (int j = 0; j < 8; j++) {
            float lo, hi;
            unpk(acc[p][j], lo, hi);
            int cc = tcol + 16 * j;
            float bv = bsm[cc];
            C0[cc] = lo + bv;
            C1[cc] = hi + bv;
        }
    }
}

// ---------------- cross-attention v2: R-split, 3 CTAs/SM ----------------
// per block: 128 rules x 64 s for one (h, b). smem 72704B.
#define QT_PITCH 132
#define KV_PITCH 76
#define AT_KT 8448
#define AT_V (AT_KT + 64 * KV_PITCH)
#define ATTN_SMEM ((AT_V + 64 * KV_PITCH) * 4)
__global__ void __launch_bounds__(256, 3) k_attn() {
    extern __shared__ float sm[];
    float* QP = sm;           // Qt[k][r] then P[s][r], pitch 132
    float* Kt = sm + AT_KT;   // [k][s] pitch 76
    float* Vs = sm + AT_V;    // [s][d] pitch 76
    const int tid = threadIdx.x;
    const int h = blockIdx.x, b = blockIdx.y, r0 = blockIdx.z * 128;
    for (int idx = tid; idx < 128 * 64; idx += 256) {
        int k = idx & 63, r = idx >> 6;
        QP[k * QT_PITCH + r] = g_Q[(size_t)(r0 + r) * DD + h * 64 + k];
    }
    for (int idx = tid; idx < 64 * 64; idx += 256) {
        int k = idx & 63, s = idx >> 6;
        Kt[k * KV_PITCH + s] = g_Kx[(size_t)(b * SS + s) * DD + h * 64 + k];
        Vs[s * KV_PITCH + k] = g_Vx[(size_t)(b * SS + s) * DD + h * 64 + k];
    }
    __syncthreads();
    const int trow = tid >> 3, tcol = tid & 7;
    const int rbase = trow * 4, sbase = tcol * 8;
    // phase 1: S tile [4 rules][8 s]
    ull acc[4][4];
#pragma unroll
    for (int j = 0; j < 4; j++)
#pragma unroll
        for (int i = 0; i < 4; i++) acc[j][i] = 0ull;
    for (int k = 0; k < 64; k++) {
        float4 q = *(const float4*)(QP + k * QT_PITCH + rbase);
        ulonglong2 ka = *(const ulonglong2*)(Kt + k * KV_PITCH + sbase);
        ulonglong2 kb = *(const ulonglong2*)(Kt + k * KV_PITCH + sbase + 4);
        float qs[4] = {q.x, q.y, q.z, q.w};
#pragma unroll
        for (int j = 0; j < 4; j++) {
            ull qd = pkdup(qs[j]);
            fma2(acc[j][0], qd, ka.x);
            fma2(acc[j][1], qd, ka.y);
            fma2(acc[j][2], qd, kb.x);
            fma2(acc[j][3], qd, kb.y);
        }
    }
    // softmax: each row's 64 s split over 8 consecutive lanes
    float p[4][8];
#pragma unroll
    for (int j = 0; j < 4; j++) {
#pragma unroll
        for (int i = 0; i < 4; i++) unpk(acc[j][i], p[j][2 * i], p[j][2 * i + 1]);
        float m = p[j][0];
#pragma unroll
        for (int i = 1; i < 8; i++) m = fmaxf(m, p[j][i]);
        m = fmaxf(m, __shfl_xor_sync(0xffffffffu, m, 1));
        m = fmaxf(m, __shfl_xor_sync(0xffffffffu, m, 2));
        m = fmaxf(m, __shfl_xor_sync(0xffffffffu, m, 4));
        float sum = 0.f;
#pragma unroll
        for (int i = 0; i < 8; i++) { p[j][i] = __expf(p[j][i] - m); sum += p[j][i]; }
        sum += __shfl_xor_sync(0xffffffffu, sum, 1);
        sum += __shfl_xor_sync(0xffffffffu, sum, 2);
        sum += __shfl_xor_sync(0xffffffffu, sum, 4);
        float inv = 1.f / sum;
#pragma unroll
        for (int i = 0; i < 8; i++) p[j][i] *= inv;
    }
    __syncthreads();   // all Qt reads done; QP becomes P[s][r]
#pragma unroll
    for (int i = 0; i < 8; i++)
        *(float4*)(QP + (sbase + i) * QT_PITCH + rbase) =
            make_float4(p[0][i], p[1][i], p[2][i], p[3][i]);
    __syncthreads();
    // phase 2: ctx tile [4 rules][8 d], d slice = sbase..sbase+7
    ull c2[4][4];
#pragma unroll
    for (int j = 0; j < 4; j++)
#pragma unroll
        for (int i = 0; i < 4; i++) c2[j][i] = 0ull;
    for (int s = 0; s < 64; s++) {
        float4 pv = *(const float4*)(QP + s * QT_PITCH + rbase);
        ulonglong2 va = *(const ulonglong2*)(Vs + s * KV_PITCH + sbase);
        ulonglong2 vb = *(const ulonglong2*)(Vs + s * KV_PITCH + sbase + 4);
        float ps[4] = {pv.x, pv.y, pv.z, pv.w};
#pragma unroll
        for (int j = 0; j < 4; j++) {
            ull pd = pkdup(ps[j]);
            fma2(c2[j][0], pd, va.x);
            fma2(c2[j][1], pd, va.y);
            fma2(c2[j][2], pd, vb.x);
            fma2(c2[j][3], pd, vb.y);
        }
    }
#pragma unroll
    for (int j = 0; j < 4; j++) {
        float o[8];
#pragma unroll
        for (int i = 0; i < 4; i++) unpk(c2[j][i], o[2 * i], o[2 * i + 1]);
        float* op = g_ctx + (size_t)(b * RR + r0 + rbase + j) * DD + h * 64 + sbase;
        *(float4*)op = make_float4(o[0], o[1], o[2], o[3]);
        *(float4*)(op + 4) = make_float4(o[4], o[5], o[6], o[7]);
    }
}

// ---------------- gathered per-class GEMM ----------------
__global__ void __launch_bounds__(256, 2)
k_hw1g() {
    const int c = blockIdx.y;
    const int cnt = g_memb_cnt[c];
    const int Mc = BB * cnt;
    const int row0 = blockIdx.x * 128;
    if (row0 >= Mc) return;
    __shared__ float As[32][130];
    __shared__ float Bs[32][128];
    __shared__ float bsm[128];
    __shared__ int rowbase[128];
    __shared__ int outbase[128];
    const int tid = threadIdx.x;
    if (tid < 128) {
        bsm[tid] = g_bo1[c * 128 + tid];
        int g = row0 + tid;
        if (g < Mc) {
            int b = g / cnt, mr = g - b * cnt;
            int ridx = g_memb_idx[c * MAXRC + mr];
            rowbase[tid] = (b * RR + ridx) * DD;
            outbase[tid] = ((c * BB + b) * MAXRC + mr) * 128;
        } else { rowbase[tid] = 0; outbase[tid] = -1; }
    }
    __syncthreads();
    const float* Wc = g_Wf + (size_t)c * DD * 128;
    const int trow = tid >> 4, tcol = tid & 15;
    ull acc[4][8];
#pragma unroll
    for (int p = 0; p < 4; p++)
#pragma unroll
        for (int j = 0; j < 8; j++) acc[p][j] = 0ull;
    for (int k0 = 0; k0 < 256; k0 += 32) {
#pragma unroll
        for (int t = 0; t < 4; t++) {
            int idx = (tid + t * 256) * 4;
            int r = idx >> 5, kk = idx & 31;
            float4 v = *(const float4*)(g_ctx + (size_t)rowbase[r] + k0 + kk);
            As[kk][r] = v.x; As[kk + 1][r] = v.y; As[kk + 2][r] = v.z; As[kk + 3][r] = v.w;
        }
#pragma unroll
        for (int t = 0; t < 4; t++) {
            int idx = (tid + t * 256) * 4;
            int rk = idx >> 7, cc = idx & 127;
            *(float4*)&Bs[rk][cc] = *(const float4*)(Wc + (size_t)(k0 + rk) * 128 + cc);
        }
        __syncthreads();
#pragma unroll
        for (int k = 0; k < 32; k++) {
            ull a2[4], b2[8];
#pragma unroll
            for (int p = 0; p < 4; p++) a2[p] = *(const ull*)&As[k][trow * 8 + 2 * p];
#pragma unroll
            for (int j = 0; j < 8; j++) b2[j] = pkdup(Bs[k][tcol + 16 * j]);
#pragma unroll
            for (int p = 0; p < 4; p++)
#pragma unroll
                for (int j = 0; j < 8; j++) fma2(acc[p][j], a2[p], b2[j]);
        }
        __syncthreads();
    }
#pragma unroll
    for (int p = 0; p < 4; p++) {
        int lr0 = trow * 8 + 2 * p;
        int ob0 = outbase[lr0], ob1 = outbase[lr0 + 1];
#pragma unroll
        for (int j = 0; j < 8; j++) {
            float lo, hi;
            unpk(acc[p][j], lo, hi);
            int cc = tcol + 16 * j;
            float bv = bsm[cc];
            if (ob0 >= 0) g_hW1c[(size_t)ob0 + cc] = lo + bv;
            if (ob1 >= 0) g_hW1c[(size_t)ob1 + cc] = hi + bv;
        }
    }
}

// ---------------- Wf[c] = Wo @ W1[c] ----------------
__global__ void __launch_bounds__(256, 2)
k_fusew(const float* __restrict__ Wo, const float* __restrict__ W1) {
    const int c = blockIdx.y;
    const int row0 = blockIdx.x * 128;
    __shared__ float As[32][130];
    __shared__ float Bs[32][128];
    const int tid = threadIdx.x;
    const float* Wc = W1 + (size_t)c * DD * 128;
    const int trow = tid >> 4, tcol = tid & 15;
    ull acc[4][8];
#pragma unroll
    for (int p = 0; p < 4; p++)
#pragma unroll
        for (int j = 0; j < 8; j++) acc[p][j] = 0ull;
    for (int k0 = 0; k0 < 256; k0 += 32) {
#pragma unroll
        for (int t = 0; t < 4; t++) {
            int idx = (tid + t * 256) * 4;
            int r = idx >> 5, kk = idx & 31;
            float4 v = *(const float4*)(Wo + (size_t)(row0 + r) * 256 + k0 + kk);
            As[kk][r] = v.x; As[kk + 1][r] = v.y; As[kk + 2][r] = v.z; As[kk + 3][r] = v.w;
        }
#pragma unroll
        for (int t = 0; t < 4; t++) {
            int idx = (tid + t * 256) * 4;
            int rk = idx >> 7, cc = idx & 127;
            *(float4*)&Bs[rk][cc] = *(const float4*)(Wc + (size_t)(k0 + rk) * 128 + cc);
        }
        __syncthreads();
#pragma unroll
        for (int k = 0; k < 32; k++) {
            ull a2[4], b2[8];
#pragma unroll
            for (int p = 0; p < 4; p++) a2[p] = *(const ull*)&As[k][trow * 8 + 2 * p];
#pragma unroll
            for (int j = 0; j < 8; j++) b2[j] = pkdup(Bs[k][tcol + 16 * j]);
#pragma unroll
            for (int p = 0; p < 4; p++)
#pragma unroll
                for (int j = 0; j < 8; j++) fma2(acc[p][j], a2[p], b2[j]);
        }
        __syncthreads();
    }
    float* Cc = g_Wf + (size_t)c * DD * 128;
#pragma unroll
    for (int p = 0; p < 4; p++) {
        float* C0 = Cc + (size_t)(row0 + trow * 8 + 2 * p) * 128;
        float* C1 = C0 + 128;
#pragma unroll
        for (int j = 0; j < 8; j++) {
            float lo, hi;
            unpk(acc[p][j], lo, hi);
            int cc = tcol + 16 * j;
            C0[cc] = lo;
            C1[cc] = hi;
        }
    }
}

// ---------------- fused prep: y==0 -> a2 projections; y==1 -> bo1 ----------------
__global__ void k_prep(const float* __restrict__ W2, const float* __restrict__ a2d,
                       const float* __restrict__ a2s, const float* __restrict__ bo,
                       const float* __restrict__ W1) {
    int c = blockIdx.x, f = threadIdx.x;
    if (blockIdx.y == 0) {
        float dv = 0.f, sv = 0.f;
        const float* wr = W2 + ((size_t)c * 128 + f) * 64;
#pragma unroll
        for (int g = 0; g < 64; g++) {
            float w = wr[g];
            dv += w * a2d[c * 64 + g];
            sv += w * a2s[c * 64 + g];
        }
        g_a2dp[c * 128 + f] = dv;
        g_a2sp[c * 128 + f] = sv;
    } else {
        const float* Wc = W1 + (size_t)c * DD * 128;
        float acc = 0.f;
        for (int e = 0; e < DD; e++) acc += bo[e] * Wc[(size_t)e * 128 + f];
        g_bo1[c * 128 + f] = acc;
    }
}

// ---------------- fused GAT stack v5: float4 aggregation, warp-per-row ----------------
#define MG_HWS 0
#define MG_WBUF 6144
#define MG_UNION 10496
#define MG_A1D 12544
#define MG_A1S 12672
#define MG_B1 12800
#define MG_AD2 12928
#define MG_AS2 13056
#define MG_D1 13184
#define MG_S1 13440
#define MG_DEN1 13696
#define MG_D2 13952
#define MG_S2 14208
#define MG_DEN2 14464
#define MG_COEF 14720
#define MG_GSUM 14976
#define MG_GVEC 15104
#define MG_LOG 15168
#define MG_MCS 15176
#define MG_MIDX 15432
#define MG_ADJB 15496
#define MG_JCS8 17800
#define MEGA_SMEM (18824 * 4)
__global__ void __launch_bounds__(512, 3)
k_mega(const float* __restrict__ a1s, const float* __restrict__ a1d,
       const float* __restrict__ b1, const float* __restrict__ W2,
       const float* __restrict__ b2, const float* __restrict__ Wl,
       const float* __restrict__ bl, float* __restrict__ out) {
    extern __shared__ float sm[];
    float* hws = sm + MG_HWS;                               // [48][128]
    float* wbufd = sm + MG_WBUF;                            // [256][17]
    float* denp = sm + MG_UNION;                            // [512] den partials
    float* gpart = sm + MG_UNION;                           // [16][128] final partials
    float* a1dv = sm + MG_A1D;
    float* a1sv = sm + MG_A1S;
    float* b1v = sm + MG_B1;
    float* ad2 = sm + MG_AD2;
    float* as2 = sm + MG_AS2;
    float* d1s = sm + MG_D1;
    float* s1s = sm + MG_S1;
    float* den1 = sm + MG_DEN1;
    float* d2s = sm + MG_D2;
    float* s2s = sm + MG_S2;
    float* den2 = sm + MG_DEN2;
    float* coef = sm + MG_COEF;
    float* gsum = sm + MG_GSUM;
    float* gvec = sm + MG_GVEC;
    float* logits = sm + MG_LOG;
    int* mcs = (int*)(sm + MG_MCS);
    int* midx = (int*)(sm + MG_MIDX);
    unsigned int* adjb = (unsigned int*)(sm + MG_ADJB);     // [256][9]
    unsigned char* jcs8 = (unsigned char*)(sm + MG_JCS8);   // [256][16]
    const int b = blockIdx.x, c = blockIdx.y, tid = threadIdx.x;
    const int warp = tid >> 5, lane = tid & 31;
    const int cnt = g_memb_cnt[c];
    const size_t base = (size_t)(c * BB + b);
    {
        const float4* src4 = (const float4*)(g_hW1c + base * MAXRC * 128);
        float4* dst4 = (float4*)hws;
        int n4 = cnt * 32;
        for (int i = tid; i < n4; i += 512) dst4[i] = src4[i];
    }
    {
        unsigned int* j32 = (unsigned int*)jcs8;
        const unsigned int* gsrc = (const unsigned int*)g_mn_jc8 + c * RR * MNCAP / 4;
        for (int i = tid; i < RR * MNCAP / 4; i += 512) j32[i] = gsrc[i];
    }
    if (tid < 128) {
        a1dv[tid] = a1d[c * 128 + tid];
        a1sv[tid] = a1s[c * 128 + tid];
        b1v[tid] = b1[c * 128 + tid];
        ad2[tid] = g_a2dp[c * 128 + tid];
        as2[tid] = g_a2sp[c * 128 + tid];
    }
    if (tid < 256) {
        d1s[tid] = 0.f; s1s[tid] = 0.f;
        mcs[tid] = g_mn_cnt[c * RR + tid];
#pragma unroll
        for (int w = 0; w < 8; w++) adjb[tid * 9 + w] = g_adjbits[tid * 8 + w];
    }
    if (tid < MAXRC) midx[tid] = g_memb_idx[c * MAXRC + tid];
    __syncthreads();
    for (int mr = warp; mr < cnt; mr += 16) {
        const float4* hp = (const float4*)(hws + mr * HW_PITCH);
        float4 x = hp[lane];
        float4 ad = ((const float4*)a1dv)[lane];
        float4 as = ((const float4*)a1sv)[lane];
        float dv = x.x * ad.x + x.y * ad.y + x.z * ad.z + x.w * ad.w;
        float sv = x.x * as.x + x.y * as.y + x.z * as.z + x.w * as.w;
#pragma unroll
        for (int o = 16; o > 0; o >>= 1) {
            dv += __shfl_xor_sync(0xffffffffu, dv, o);
            sv += __shfl_xor_sync(0xffffffffu, sv, o);
        }
        if (lane == 0) { int ridx = midx[mr]; d1s[ridx] = dv; s1s[ridx] = sv; }
    }
    __syncthreads();
    {
        int half = tid >> 8, i = tid & 255;
        float di = d1s[i];
        float dsum = 0.f;
#pragma unroll
        for (int w = half * 4; w < half * 4 + 4; w++) {
            unsigned int bits = adjb[i * 9 + w];
            while (bits) {
                int t = __ffs(bits) - 1;
                bits &= bits - 1;
                dsum += __expf(lrelu02(di + s1s[w * 32 + t]));
            }
        }
        denp[tid] = dsum;
    }
    __syncthreads();
    if (tid < 256) {
        float inv = 1.f / (denp[tid] + denp[tid + 256]);
        int mc = mcs[tid];
        float di = d1s[tid];
        const unsigned char* jr = jcs8 + tid * 16;
        for (int m = 0; m < mc; m++)
            wbufd[tid * 17 + m] = __expf(lrelu02(di + s1s[midx[jr[m]]])) * inv;
    }
    __syncthreads();
    {
        float4 bb = ((const float4*)b1v)[lane];
        float4 ad = ((const float4*)ad2)[lane];
        float4 as = ((const float4*)as2)[lane];
#pragma unroll 4
        for (int it = 0; it < 16; it++) {
            int i = it * 16 + warp;
            int mc = mcs[i];
            float4 h;
            if (mc == 0) {
                h.x = fmaxf(bb.x, 0.f); h.y = fmaxf(bb.y, 0.f);
                h.z = fmaxf(bb.z, 0.f); h.w = fmaxf(bb.w, 0.f);
            } else {
                const float* wd = wbufd + i * 17;
                const unsigned char* jr = jcs8 + i * 16;
                float4 acc = make_float4(0.f, 0.f, 0.f, 0.f);
                for (int m = 0; m < mc; m++) {
                    float w = wd[m];
                    float4 hv = *(const float4*)(hws + (int)jr[m] * HW_PITCH + 4 * lane);
                    acc.x += w * hv.x; acc.y += w * hv.y;
                    acc.z += w * hv.z; acc.w += w * hv.w;
                }
                h.x = fmaxf(acc.x + bb.x, 0.f); h.y = fmaxf(acc.y + bb.y, 0.f);
                h.z = fmaxf(acc.z + bb.z, 0.f); h.w = fmaxf(acc.w + bb.w, 0.f);
            }
            float dv = h.x * ad.x + h.y * ad.y + h.z * ad.z + h.w * ad.w;
            float sv = h.x * as.x + h.y * as.y + h.z * as.z + h.w * as.w;
#pragma unroll
            for (int o = 16; o > 0; o >>= 1) {
                dv += __shfl_xor_sync(0xffffffffu, dv, o);
                sv += __shfl_xor_sync(0xffffffffu, sv, o);
            }
            if (lane == 0) { d2s[i] = dv; s2s[i] = sv; }
        }
    }
    __syncthreads();
    {
        int half = tid >> 8, i = tid & 255;
        float di = d2s[i];
        float dsum = 0.f;
#pragma unroll
        for (int w = half * 4; w < half * 4 + 4; w++) {
            unsigned int bits = adjb[i * 9 + w];
            while (bits) {
                int t = __ffs(bits) - 1;
                bits &= bits - 1;
                dsum += __expf(lrelu02(di + s2s[w * 32 + t]));
            }
        }
        denp[tid] = dsum;
    }
    __syncthreads();
    if (tid < 256) den2[tid] = 1.f / (denp[tid] + denp[tid + 256]);
    __syncthreads();
    {
        int half = tid >> 8, j = tid & 255;
        float sj = s2s[j];
        float cs = 0.f;
#pragma unroll
        for (int w = half * 4; w < half * 4 + 4; w++) {
            unsigned int bits = adjb[j * 9 + w];
            while (bits) {
                int t = __ffs(bits) - 1;
                bits &= bits - 1;
                int i2 = w * 32 + t;
                cs += __expf(lrelu02(d2s[i2] + sj)) * den2[i2];
            }
        }
        denp[tid] = cs;
    }
    __syncthreads();
    if (tid < 256) coef[tid] = denp[tid] + denp[tid + 256];
    __syncthreads();
    {
        float4 bb = ((const float4*)b1v)[lane];
        float4 p = make_float4(0.f, 0.f, 0.f, 0.f);
#pragma unroll 4
        for (int it = 0; it < 16; it++) {
            int i = it * 16 + warp;
            int mc = mcs[i];
            float cf = coef[i];
            float4 h;
            if (mc == 0) {
                h.x = fmaxf(bb.x, 0.f); h.y = fmaxf(bb.y, 0.f);
                h.z = fmaxf(bb.z, 0.f); h.w = fmaxf(bb.w, 0.f);
            } else {
                const float* wd = wbufd + i * 17;
                const unsigned char* jr = jcs8 + i * 16;
                float4 acc = make_float4(0.f, 0.f, 0.f, 0.f);
                for (int m = 0; m < mc; m++) {
                    float w = wd[m];
                    float4 hv = *(const float4*)(hws + (int)jr[m] * HW_PITCH + 4 * lane);
                    acc.x += w * hv.x; acc.y += w * hv.y;
                    acc.z += w * hv.z; acc.w += w * hv.w;
                }
                h.x = fmaxf(acc.x + bb.x, 0.f); h.y = fmaxf(acc.y + bb.y, 0.f);
                h.z = fmaxf(acc.z + bb.z, 0.f); h.w = fmaxf(acc.w + bb.w, 0.f);
            }
            p.x += cf * h.x; p.y += cf * h.y; p.z += cf * h.z; p.w += cf * h.w;
        }
        __syncthreads();  // coef reads complete before union region becomes gpart
        ((float4*)(gpart + warp * 128))[lane] = p;
    }
    __syncthreads();
    if (tid < 128) {
        float s = 0.f;
#pragma unroll
        for (int w = 0; w < 16; w++) s += gpart[w * 128 + tid];
        gsum[tid] = s;
    }
    __syncthreads();
    if (tid < 64) {
        float acc = 0.f;
        for (int f = 0; f < 128; f++) acc += gsum[f] * W2[((size_t)c * 128 + f) * 64 + tid];
        gvec[tid] = acc + 256.f * b2[c * 64 + tid];
    }
    __syncthreads();
    if (tid < KKC) {
        float l = 0.f;
        for (int t = 0; t < 64; t++) l += gvec[t] * Wl[(c * 64 + t) * KKC + tid];
        logits[tid] = l + 256.f * bl[c * KKC + tid];
    }
    __syncthreads();
    if (tid == 0) {
        float mx = logits[0];
#pragma unroll
        for (int k = 1; k < KKC; k++) mx = fmaxf(mx, logits[k]);
        float se = 0.f;
#pragma unroll
        for (int k = 0; k < KKC; k++) se += __expf(logits[k] - mx);
        float lse = logf(se) + mx;
#pragma unroll
        for (int k = 0; k < KKC; k++) out[base * KKC + k] = logits[k] - lse;
    }
}

// ---------------- launcher ----------------
extern "C" void kernel_launch(void* const* d_in, const int* in_sizes, int n_in,
                              void* d_out, int out_size) {
    const float* vis = (const float*)d_in[0];
    const float* basic = (const float*)d_in[1];
    const float* crucial = (const float*)d_in[2];
    const float* Wtb = (const float*)d_in[3];
    const float* btb = (const float*)d_in[4];
    const float* Wtk = (const float*)d_in[5];
    const float* btk = (const float*)d_in[6];
    const float* Wq = (const float*)d_in[7];
    const float* bq = (const float*)d_in[8];
    const float* Wk = (const float*)d_in[9];
    const float* bk = (const float*)d_in[10];
    const float* Wv = (const float*)d_in[11];
    const float* bv = (const float*)d_in[12];
    const float* Wo = (const float*)d_in[13];
    const float* bo = (const float*)d_in[14];
    const float* W1 = (const float*)d_in[15];
    const float* a1s = (const float*)d_in[16];
    const float* a1d = (const float*)d_in[17];
    const float* b1 = (const float*)d_in[18];
    const float* W2 = (const float*)d_in[19];
    const float* a2s = (const float*)d_in[20];
    const float* a2d = (const float*)d_in[21];
    const float* b2 = (const float*)d_in[22];
    const float* Wl = (const float*)d_in[23];
    const float* bl = (const float*)d_in[24];
    const void* adjraw = d_in[25];
    const int* mask = (const int*)d_in[26];
    float* out = (float*)d_out;

    void *p_Kx, *p_Vx;
    cudaGetSymbolAddress(&p_Kx, g_Kx);
    cudaGetSymbolAddress(&p_Vx, g_Vx);

    cudaFuncSetAttribute((const void*)k_attn, cudaFuncAttributeMaxDynamicSharedMemorySize, ATTN_SMEM);
    cudaFuncSetAttribute((const void*)k_mega, cudaFuncAttributeMaxDynamicSharedMemorySize, MEGA_SMEM);

    // profiled slot (#4) = k_attn (new version)
    k_rule<<<RR, 256>>>(basic, crucial, Wtb, btb, Wtk, btk, Wq, bq);
    k_gemm256<<<dim3(2, 128), 256>>>(vis, Wk, bk, (float*)p_Kx);
    k_gemm256<<<dim3(2, 128), 256>>>(vis, Wv, bv, (float*)p_Vx);
    k_attn<<<dim3(4, BB, 2), 256, ATTN_SMEM>>>();
    k_sniff<<<1, 256>>>(adjraw);
    k_csr<<<RR, 256>>>(adjraw);
    k_memb<<<CC, 256>>>(mask);
    k_prep<<<dim3(CC, 2), 128>>>(W2, a2d, a2s, bo, W1);
    k_fusew<<<dim3(2, CC), 256>>>(Wo, W1);
    k_hw1g<<<dim3(96, CC), 256>>>();
    k_mega<<<dim3(BB, CC), 512, MEGA_SMEM>>>(a1s, a1d, b1, W2, b2, Wl, bl, out);
}

// round 15
// speedup vs baseline: 1.0747x; 1.0747x over previous
#include <cuda_runtime.h>
#include <cstdint>
#include <cstddef>

#define BB 256
#define SS 64
#define RR 256
#define VV 2000
#define CC 10
#define KKC 6
#define DD 256
#define MAXRC 48
#define MNCAP 16
#define HW_PITCH 128

typedef unsigned long long ull;

// ---------------- scratch (device globals) ----------------
__device__ float g_Q[RR * DD];
__device__ float g_Kx[BB * SS * DD];
__device__ float g_Vx[BB * SS * DD];
__device__ float g_ctx[(size_t)BB * RR * DD];
__device__ int g_adjflag;
__device__ unsigned int g_adjbits[RR * 8];
__device__ int g_nbr_cnt[RR];
__device__ int g_nbr[RR * RR];
__device__ int g_memb_cnt[CC];
__device__ int g_memb_idx[CC * MAXRC];
__device__ int g_memb_inv[CC * RR];
__device__ int g_mn_cnt[CC * RR];
__device__ unsigned char g_mn_jc8[CC * RR * MNCAP];
__device__ float g_hW1c[(size_t)CC * BB * MAXRC * 128];
__device__ float g_a2dp[CC * 128];
__device__ float g_a2sp[CC * 128];
__device__ float g_Wf[CC * DD * 128];    // Wo @ W1[c]
__device__ float g_bo1[CC * 128];        // bo @ W1[c]

__device__ __forceinline__ float lrelu02(float x) { return x > 0.f ? x : 0.2f * x; }
__device__ __forceinline__ ull pkdup(float x) { ull r; asm("mov.b64 %0,{%1,%1};" : "=l"(r) : "f"(x)); return r; }
__device__ __forceinline__ void fma2(ull& d, ull a, ull b) { asm("fma.rn.f32x2 %0,%1,%2,%0;" : "+l"(d) : "l"(a), "l"(b)); }
__device__ __forceinline__ void unpk(ull v, float& lo, float& hi) { asm("mov.b64 {%0,%1},%2;" : "=f"(lo), "=f"(hi) : "l"(v)); }

// ---------------- adj dtype sniff ----------------
__global__ void k_sniff(const void* __restrict__ adjraw) {
    __shared__ int cntA, cntB;
    int tid = threadIdx.x;
    if (tid == 0) { cntA = 0; cntB = 0; }
    __syncthreads();
    const uint4* p = (const uint4*)adjraw;
    int a = 0, b = 0;
    for (int i = tid; i < RR * RR / 16; i += 256) {
        uint4 v = p[i];
        unsigned int w[4] = {v.x, v.y, v.z, v.w};
#pragma unroll
        for (int q = 0; q < 4; q++) {
            a += ((w[q] & 0xFFu) != 0);
            b += (((w[q] >> 8) & 0xFFu) != 0) + (((w[q] >> 16) & 0xFFu) != 0) + ((w[q] >> 24) != 0);
        }
    }
    atomicAdd(&cntA, a);
    atomicAdd(&cntB, b);
    __syncthreads();
    if (tid == 0) {
        if (cntB == 0) g_adjflag = 0;
        else if (cntA == 0) g_adjflag = 1;
        else g_adjflag = 2;
    }
}

// ---------------- adjacency CSR + bitmask via ballot ----------------
__global__ void k_csr(const void* __restrict__ adjraw) {
    __shared__ unsigned int words[8];
    __shared__ int base[8];
    const int r = blockIdx.x, tid = threadIdx.x;
    const int warp = tid >> 5, lane = tid & 31;
    const int flag = g_adjflag;
    bool nz;
    if (flag == 0) nz = ((const int*)adjraw)[r * RR + tid] != 0;
    else if (flag == 1) nz = ((const float*)adjraw)[r * RR + tid] != 0.f;
    else nz = ((const unsigned char*)adjraw)[r * RR + tid] != 0;
    unsigned int ball = __ballot_sync(0xffffffffu, nz);
    if (lane == 0) words[warp] = ball;
    __syncthreads();
    if (tid == 0) {
        int s = 0;
#pragma unroll
        for (int w = 0; w < 8; w++) { base[w] = s; s += __popc(words[w]); }
        g_nbr_cnt[r] = s;
    }
    if (tid < 8) g_adjbits[r * 8 + tid] = words[tid];
    __syncthreads();
    if (nz) {
        int pos = base[warp] + __popc(ball & ((1u << lane) - 1));
        g_nbr[r * RR + pos] = tid;
    }
}

// ---------------- per-class membership + u8 member-neighbor lists ----------------
__global__ void k_memb(const int* __restrict__ mask) {
    __shared__ unsigned int words[8];
    __shared__ int base[8];
    __shared__ int invsm[RR];
    const int c = blockIdx.x, tid = threadIdx.x;
    const int warp = tid >> 5, lane = tid & 31;
    bool mem = mask[c * RR + tid] != 0;
    unsigned int ball = __ballot_sync(0xffffffffu, mem);
    if (lane == 0) words[warp] = ball;
    __syncthreads();
    if (tid == 0) {
        int s = 0;
#pragma unroll
        for (int w = 0; w < 8; w++) { base[w] = s; s += __popc(words[w]); }
        g_memb_cnt[c] = s < MAXRC ? s : MAXRC;
    }
    __syncthreads();
    int inv = -1;
    if (mem) {
        int pos = base[warp] + __popc(ball & ((1u << lane) - 1));
        if (pos < MAXRC) { inv = pos; g_memb_idx[c * MAXRC + pos] = tid; }
    }
    invsm[tid] = inv;
    g_memb_inv[c * RR + tid] = inv;
    __syncthreads();
    int i = tid;
    int deg = g_nbr_cnt[i];
    const int* nb = g_nbr + i * RR;
    int mc = 0;
    for (int m = 0; m < deg; m++) {
        int j = nb[m];
        int jc = invsm[j];
        if (jc >= 0 && mc < MNCAP) {
            g_mn_jc8[(c * RR + i) * MNCAP + mc] = (unsigned char)jc;
            mc++;
        }
    }
    for (int m = mc; m < MNCAP; m++) g_mn_jc8[(c * RR + i) * MNCAP + m] = 0;
    g_mn_cnt[c * RR + i] = mc;
}

// ---------------- rule embedding fused with scaled Q projection ----------------
__global__ void k_rule(const float* __restrict__ basic, const float* __restrict__ crucial,
                       const float* __restrict__ Wtb, const float* __restrict__ btb,
                       const float* __restrict__ Wtk, const float* __restrict__ btk,
                       const float* __restrict__ Wq, const float* __restrict__ bq) {
    __shared__ int nzb[64], nzc[64];
    __shared__ float vb[64], vc[64];
    __shared__ int cb[256], cc2[256];
    __shared__ int totb, totc;
    __shared__ float rulesm[256];
    int r = blockIdx.x, tid = threadIdx.x;
    const float* br = basic + (size_t)r * VV;
    const float* cr = crucial + (size_t)r * VV;
    int nb = 0, nc = 0;
    int v0 = tid * 8;
#pragma unroll
    for (int t = 0; t < 8; t++) {
        int v = v0 + t;
        if (v < VV) { if (br[v] != 0.f) nb++; if (cr[v] != 0.f) nc++; }
    }
    cb[tid] = nb; cc2[tid] = nc;
    __syncthreads();
    if (tid == 0) {
        int s = 0;
        for (int i = 0; i < 256; i++) { int t = cb[i]; cb[i] = s; s += t; }
        totb = s < 64 ? s : 64;
        s = 0;
        for (int i = 0; i < 256; i++) { int t = cc2[i]; cc2[i] = s; s += t; }
        totc = s < 64 ? s : 64;
    }
    __syncthreads();
    {
        int ob = cb[tid], oc = cc2[tid];
#pragma unroll
        for (int t = 0; t < 8; t++) {
            int v = v0 + t;
            if (v < VV) {
                if (br[v] != 0.f && ob < 64) { nzb[ob] = v; vb[ob] = br[v]; ob++; }
                if (cr[v] != 0.f && oc < 64) { nzc[oc] = v; vc[oc] = cr[v]; oc++; }
            }
        }
    }
    __syncthreads();
    int d = tid;
    float acc = btb[d] + btk[d];
    int tb = totb, tc = totc;
    for (int i = 0; i < tb; i++) acc += vb[i] * Wtb[(size_t)nzb[i] * DD + d];
    for (int i = 0; i < tc; i++) acc += vc[i] * Wtk[(size_t)nzc[i] * DD + d];
    rulesm[d] = acc;
    __syncthreads();
    float q = bq[d];
#pragma unroll 4
    for (int e = 0; e < 256; e++) q += rulesm[e] * Wq[(size_t)e * DD + d];
    g_Q[(size_t)r * DD + d] = q * 0.125f;
}

// ---------------- f32x2 GEMM, N=K=256, z-batched K/V projections ----------------
__global__ void __launch_bounds__(256, 2)
k_gemmKV(const float* __restrict__ A,
         const float* __restrict__ Wk, const float* __restrict__ bk, float* __restrict__ Kx,
         const float* __restrict__ Wv, const float* __restrict__ bv, float* __restrict__ Vx) {
    const float* W = blockIdx.z ? Wv : Wk;
    const float* bias = blockIdx.z ? bv : bk;
    float* C = blockIdx.z ? Vx : Kx;
    __shared__ float As[32][130];
    __shared__ float Bs[32][128];
    __shared__ float bsm[128];
    const int tid = threadIdx.x;
    const int row0 = blockIdx.y * 128, col0 = blockIdx.x * 128;
    const int trow = tid >> 4, tcol = tid & 15;
    if (tid < 128) bsm[tid] = bias[col0 + tid];
    ull acc[4][8];
#pragma unroll
    for (int p = 0; p < 4; p++)
#pragma unroll
        for (int j = 0; j < 8; j++) acc[p][j] = 0ull;
    for (int k0 = 0; k0 < 256; k0 += 32) {
#pragma unroll
        for (int t = 0; t < 4; t++) {
            int idx = (tid + t * 256) * 4;
            int r = idx >> 5, kk = idx & 31;
            float4 v = *(const float4*)(A + (size_t)(row0 + r) * 256 + k0 + kk);
            As[kk][r] = v.x; As[kk + 1][r] = v.y; As[kk + 2][r] = v.z; As[kk + 3][r] = v.w;
        }
#pragma unroll
        for (int t = 0; t < 4; t++) {
            int idx = (tid + t * 256) * 4;
            int rk = idx >> 7, cc = idx & 127;
            *(float4*)&Bs[rk][cc] = *(const float4*)(W + (size_t)(k0 + rk) * 256 + col0 + cc);
        }
        __syncthreads();
#pragma unroll
        for (int k = 0; k < 32; k++) {
            ull a2[4], b2[8];
#pragma unroll
            for (int p = 0; p < 4; p++) a2[p] = *(const ull*)&As[k][trow * 8 + 2 * p];
#pragma unroll
            for (int j = 0; j < 8; j++) b2[j] = pkdup(Bs[k][tcol + 16 * j]);
#pragma unroll
            for (int p = 0; p < 4; p++)
#pragma unroll
                for (int j = 0; j < 8; j++) fma2(acc[p][j], a2[p], b2[j]);
        }
        __syncthreads();
    }
#pragma unroll
    for (int p = 0; p < 4; p++) {
        float* C0 = C + (size_t)(row0 + trow * 8 + 2 * p) * 256 + col0;
        float* C1 = C0 + 256;
#pragma unroll
        for (int j = 0; j < 8; j++) {
            float lo, hi;
            unpk(acc[p][j], lo, hi);
            int cc = tcol + 16 * j;
            float bv2 = bsm[cc];
            C0[cc] = lo + bv2;
            C1[cc] = hi + bv2;
        }
    }
}

// ---------------- register-tiled cross-attention per (h, b) [R13 winner] ----------------
#define QT_PITCH 260
#define PT_PITCH 264
#define KV_PITCH 74
#define AT_KT (64 * PT_PITCH)
#define AT_V (AT_KT + 64 * KV_PITCH)
#define ATTN_SMEM ((AT_V + 64 * KV_PITCH) * 4)
__global__ void __launch_bounds__(256, 2) k_attn() {
    extern __shared__ float sm[];
    float* QP = sm;
    float* Kt = sm + AT_KT;
    float* Vs = sm + AT_V;
    const int tid = threadIdx.x;
    const int h = blockIdx.x, b = blockIdx.y;
    for (int idx = tid; idx < 256 * 64; idx += 256) {
        int k = idx & 63, r = idx >> 6;
        QP[k * QT_PITCH + r] = g_Q[(size_t)r * DD + h * 64 + k];
    }
    for (int idx = tid; idx < 64 * 64; idx += 256) {
        int k = idx & 63, s = idx >> 6;
        Kt[k * KV_PITCH + s] = g_Kx[(size_t)(b * SS + s) * DD + h * 64 + k];
        Vs[s * KV_PITCH + k] = g_Vx[(size_t)(b * SS + s) * DD + h * 64 + k];
    }
    __syncthreads();
    const int trow = tid >> 3, tcol = tid & 7;
    const int rbase = trow * 8, sbase = tcol * 8;
    ull acc[8][4];
#pragma unroll
    for (int r = 0; r < 8; r++)
#pragma unroll
        for (int j = 0; j < 4; j++) acc[r][j] = 0ull;
    for (int k = 0; k < 64; k++) {
        const float4* qr = (const float4*)(QP + k * QT_PITCH + rbase);
        float4 qa = qr[0], qb = qr[1];
        const ull* kp = (const ull*)(Kt + k * KV_PITCH + sbase);
        ull b0 = kp[0], b1 = kp[1], b2 = kp[2], b3 = kp[3];
        float qs[8] = {qa.x, qa.y, qa.z, qa.w, qb.x, qb.y, qb.z, qb.w};
#pragma unroll
        for (int r = 0; r < 8; r++) {
            ull qd = pkdup(qs[r]);
            fma2(acc[r][0], qd, b0);
            fma2(acc[r][1], qd, b1);
            fma2(acc[r][2], qd, b2);
            fma2(acc[r][3], qd, b3);
        }
    }
    float p[8][8];
#pragma unroll
    for (int r = 0; r < 8; r++) {
#pragma unroll
        for (int j = 0; j < 4; j++) unpk(acc[r][j], p[r][2 * j], p[r][2 * j + 1]);
        float m = p[r][0];
#pragma unroll
        for (int j = 1; j < 8; j++) m = fmaxf(m, p[r][j]);
        m = fmaxf(m, __shfl_xor_sync(0xffffffffu, m, 1));
        m = fmaxf(m, __shfl_xor_sync(0xffffffffu, m, 2));
        m = fmaxf(m, __shfl_xor_sync(0xffffffffu, m, 4));
        float sum = 0.f;
#pragma unroll
        for (int j = 0; j < 8; j++) { p[r][j] = __expf(p[r][j] - m); sum += p[r][j]; }
        sum += __shfl_xor_sync(0xffffffffu, sum, 1);
        sum += __shfl_xor_sync(0xffffffffu, sum, 2);
        sum += __shfl_xor_sync(0xffffffffu, sum, 4);
        float inv = 1.f / sum;
#pragma unroll
        for (int j = 0; j < 8; j++) p[r][j] *= inv;
    }
    __syncthreads();
#pragma unroll
    for (int i = 0; i < 8; i++) {
        float* dst = QP + (sbase + i) * PT_PITCH + rbase;
        *(float4*)dst = make_float4(p[0][i], p[1][i], p[2][i], p[3][i]);
        *(float4*)(dst + 4) = make_float4(p[4][i], p[5][i], p[6][i], p[7][i]);
    }
    __syncthreads();
    ull c2[8][4];
#pragma unroll
    for (int r = 0; r < 8; r++)
#pragma unroll
        for (int j = 0; j < 4; j++) c2[r][j] = 0ull;
    for (int s = 0; s < 64; s++) {
        const float* pr = QP + s * PT_PITCH + rbase;
        float4 pa = *(const float4*)pr;
        float4 pb = *(const float4*)(pr + 4);
        const ull* vp = (const ull*)(Vs + s * KV_PITCH + sbase);
        ull v0 = vp[0], v1 = vp[1], v2 = vp[2], v3 = vp[3];
        float pv[8] = {pa.x, pa.y, pa.z, pa.w, pb.x, pb.y, pb.z, pb.w};
#pragma unroll
        for (int r = 0; r < 8; r++) {
            ull pd = pkdup(pv[r]);
            fma2(c2[r][0], pd, v0);
            fma2(c2[r][1], pd, v1);
            fma2(c2[r][2], pd, v2);
            fma2(c2[r][3], pd, v3);
        }
    }
#pragma unroll
    for (int r = 0; r < 8; r++) {
        float o[8];
#pragma unroll
        for (int j = 0; j < 4; j++) unpk(c2[r][j], o[2 * j], o[2 * j + 1]);
        float* op = g_ctx + (size_t)(b * RR + rbase + r) * DD + h * 64 + sbase;
        *(float4*)op = make_float4(o[0], o[1], o[2], o[3]);
        *(float4*)(op + 4) = make_float4(o[4], o[5], o[6], o[7]);
    }
}

// ---------------- gathered per-class GEMM ----------------
__global__ void __launch_bounds__(256, 2)
k_hw1g() {
    const int c = blockIdx.y;
    const int cnt = g_memb_cnt[c];
    const int Mc = BB * cnt;
    const int row0 = blockIdx.x * 128;
    if (row0 >= Mc) return;
    __shared__ float As[32][130];
    __shared__ float Bs[32][128];
    __shared__ float bsm[128];
    __shared__ int rowbase[128];
    __shared__ int outbase[128];
    const int tid = threadIdx.x;
    if (tid < 128) {
        bsm[tid] = g_bo1[c * 128 + tid];
        int g = row0 + tid;
        if (g < Mc) {
            int b = g / cnt, mr = g - b * cnt;
            int ridx = g_memb_idx[c * MAXRC + mr];
            rowbase[tid] = (b * RR + ridx) * DD;
            outbase[tid] = ((c * BB + b) * MAXRC + mr) * 128;
        } else { rowbase[tid] = 0; outbase[tid] = -1; }
    }
    __syncthreads();
    const float* Wc = g_Wf + (size_t)c * DD * 128;
    const int trow = tid >> 4, tcol = tid & 15;
    ull acc[4][8];
#pragma unroll
    for (int p = 0; p < 4; p++)
#pragma unroll
        for (int j = 0; j < 8; j++) acc[p][j] = 0ull;
    for (int k0 = 0; k0 < 256; k0 += 32) {
#pragma unroll
        for (int t = 0; t < 4; t++) {
            int idx = (tid + t * 256) * 4;
            int r = idx >> 5, kk = idx & 31;
            float4 v = *(const float4*)(g_ctx + (size_t)rowbase[r] + k0 + kk);
            As[kk][r] = v.x; As[kk + 1][r] = v.y; As[kk + 2][r] = v.z; As[kk + 3][r] = v.w;
        }
#pragma unroll
        for (int t = 0; t < 4; t++) {
            int idx = (tid + t * 256) * 4;
            int rk = idx >> 7, cc = idx & 127;
            *(float4*)&Bs[rk][cc] = *(const float4*)(Wc + (size_t)(k0 + rk) * 128 + cc);
        }
        __syncthreads();
#pragma unroll
        for (int k = 0; k < 32; k++) {
            ull a2[4], b2[8];
#pragma unroll
            for (int p = 0; p < 4; p++) a2[p] = *(const ull*)&As[k][trow * 8 + 2 * p];
#pragma unroll
            for (int j = 0; j < 8; j++) b2[j] = pkdup(Bs[k][tcol + 16 * j]);
#pragma unroll
            for (int p = 0; p < 4; p++)
#pragma unroll
                for (int j = 0; j < 8; j++) fma2(acc[p][j], a2[p], b2[j]);
        }
        __syncthreads();
    }
#pragma unroll
    for (int p = 0; p < 4; p++) {
        int lr0 = trow * 8 + 2 * p;
        int ob0 = outbase[lr0], ob1 = outbase[lr0 + 1];
#pragma unroll
        for (int j = 0; j < 8; j++) {
            float lo, hi;
            unpk(acc[p][j], lo, hi);
            int cc = tcol + 16 * j;
            float bv = bsm[cc];
            if (ob0 >= 0) g_hW1c[(size_t)ob0 + cc] = lo + bv;
            if (ob1 >= 0) g_hW1c[(size_t)ob1 + cc] = hi + bv;
        }
    }
}

// ---------------- Wf[c] = Wo @ W1[c] ----------------
__global__ void __launch_bounds__(256, 2)
k_fusew(const float* __restrict__ Wo, const float* __restrict__ W1) {
    const int c = blockIdx.y;
    const int row0 = blockIdx.x * 128;
    __shared__ float As[32][130];
    __shared__ float Bs[32][128];
    const int tid = threadIdx.x;
    const float* Wc = W1 + (size_t)c * DD * 128;
    const int trow = tid >> 4, tcol = tid & 15;
    ull acc[4][8];
#pragma unroll
    for (int p = 0; p < 4; p++)
#pragma unroll
        for (int j = 0; j < 8; j++) acc[p][j] = 0ull;
    for (int k0 = 0; k0 < 256; k0 += 32) {
#pragma unroll
        for (int t = 0; t < 4; t++) {
            int idx = (tid + t * 256) * 4;
            int r = idx >> 5, kk = idx & 31;
            float4 v = *(const float4*)(Wo + (size_t)(row0 + r) * 256 + k0 + kk);
            As[kk][r] = v.x; As[kk + 1][r] = v.y; As[kk + 2][r] = v.z; As[kk + 3][r] = v.w;
        }
#pragma unroll
        for (int t = 0; t < 4; t++) {
            int idx = (tid + t * 256) * 4;
            int rk = idx >> 7, cc = idx & 127;
            *(float4*)&Bs[rk][cc] = *(const float4*)(Wc + (size_t)(k0 + rk) * 128 + cc);
        }
        __syncthreads();
#pragma unroll
        for (int k = 0; k < 32; k++) {
            ull a2[4], b2[8];
#pragma unroll
            for (int p = 0; p < 4; p++) a2[p] = *(const ull*)&As[k][trow * 8 + 2 * p];
#pragma unroll
            for (int j = 0; j < 8; j++) b2[j] = pkdup(Bs[k][tcol + 16 * j]);
#pragma unroll
            for (int p = 0; p < 4; p++)
#pragma unroll
                for (int j = 0; j < 8; j++) fma2(acc[p][j], a2[p], b2[j]);
        }
        __syncthreads();
    }
    float* Cc = g_Wf + (size_t)c * DD * 128;
#pragma unroll
    for (int p = 0; p < 4; p++) {
        float* C0 = Cc + (size_t)(row0 + trow * 8 + 2 * p) * 128;
        float* C1 = C0 + 128;
#pragma unroll
        for (int j = 0; j < 8; j++) {
            float lo, hi;
            unpk(acc[p][j], lo, hi);
            int cc = tcol + 16 * j;
            C0[cc] = lo;
            C1[cc] = hi;
        }
    }
}

// ---------------- fused prep: y==0 -> a2 projections; y==1 -> bo1 ----------------
__global__ void k_prep(const float* __restrict__ W2, const float* __restrict__ a2d,
                       const float* __restrict__ a2s, const float* __restrict__ bo,
                       const float* __restrict__ W1) {
    int c = blockIdx.x, f = threadIdx.x;
    if (blockIdx.y == 0) {
        float dv = 0.f, sv = 0.f;
        const float* wr = W2 + ((size_t)c * 128 + f) * 64;
#pragma unroll
        for (int g = 0; g < 64; g++) {
            float w = wr[g];
            dv += w * a2d[c * 64 + g];
            sv += w * a2s[c * 64 + g];
        }
        g_a2dp[c * 128 + f] = dv;
        g_a2sp[c * 128 + f] = sv;
    } else {
        const float* Wc = W1 + (size_t)c * DD * 128;
        float acc = 0.f;
        for (int e = 0; e < DD; e++) acc += bo[e] * Wc[(size_t)e * 128 + f];
        g_bo1[c * 128 + f] = acc;
    }
}

// ---------------- fused GAT stack v5: float4 aggregation, warp-per-row ----------------
#define MG_HWS 0
#define MG_WBUF 6144
#define MG_UNION 10496
#define MG_A1D 12544
#define MG_A1S 12672
#define MG_B1 12800
#define MG_AD2 12928
#define MG_AS2 13056
#define MG_D1 13184
#define MG_S1 13440
#define MG_DEN1 13696
#define MG_D2 13952
#define MG_S2 14208
#define MG_DEN2 14464
#define MG_COEF 14720
#define MG_GSUM 14976
#define MG_GVEC 15104
#define MG_LOG 15168
#define MG_MCS 15176
#define MG_MIDX 15432
#define MG_ADJB 15496
#define MG_JCS8 17800
#define MEGA_SMEM (18824 * 4)
__global__ void __launch_bounds__(512, 3)
k_mega(const float* __restrict__ a1s, const float* __restrict__ a1d,
       const float* __restrict__ b1, const float* __restrict__ W2,
       const float* __restrict__ b2, const float* __restrict__ Wl,
       const float* __restrict__ bl, float* __restrict__ out) {
    extern __shared__ float sm[];
    float* hws = sm + MG_HWS;                               // [48][128]
    float* wbufd = sm + MG_WBUF;                            // [256][17]
    float* denp = sm + MG_UNION;                            // [512] den partials
    float* gpart = sm + MG_UNION;                           // [16][128] final partials
    float* a1dv = sm + MG_A1D;
    float* a1sv = sm + MG_A1S;
    float* b1v = sm + MG_B1;
    float* ad2 = sm + MG_AD2;
    float* as2 = sm + MG_AS2;
    float* d1s = sm + MG_D1;
    float* s1s = sm + MG_S1;
    float* den1 = sm + MG_DEN1;
    float* d2s = sm + MG_D2;
    float* s2s = sm + MG_S2;
    float* den2 = sm + MG_DEN2;
    float* coef = sm + MG_COEF;
    float* gsum = sm + MG_GSUM;
    float* gvec = sm + MG_GVEC;
    float* logits = sm + MG_LOG;
    int* mcs = (int*)(sm + MG_MCS);
    int* midx = (int*)(sm + MG_MIDX);
    unsigned int* adjb = (unsigned int*)(sm + MG_ADJB);     // [256][9]
    unsigned char* jcs8 = (unsigned char*)(sm + MG_JCS8);   // [256][16]
    const int b = blockIdx.x, c = blockIdx.y, tid = threadIdx.x;
    const int warp = tid >> 5, lane = tid & 31;
    const int cnt = g_memb_cnt[c];
    const size_t base = (size_t)(c * BB + b);
    {
        const float4* src4 = (const float4*)(g_hW1c + base * MAXRC * 128);
        float4* dst4 = (float4*)hws;
        int n4 = cnt * 32;
        for (int i = tid; i < n4; i += 512) dst4[i] = src4[i];
    }
    {
        unsigned int* j32 = (unsigned int*)jcs8;
        const unsigned int* gsrc = (const unsigned int*)g_mn_jc8 + c * RR * MNCAP / 4;
        for (int i = tid; i < RR * MNCAP / 4; i += 512) j32[i] = gsrc[i];
    }
    if (tid < 128) {
        a1dv[tid] = a1d[c * 128 + tid];
        a1sv[tid] = a1s[c * 128 + tid];
        b1v[tid] = b1[c * 128 + tid];
        ad2[tid] = g_a2dp[c * 128 + tid];
        as2[tid] = g_a2sp[c * 128 + tid];
    }
    if (tid < 256) {
        d1s[tid] = 0.f; s1s[tid] = 0.f;
        mcs[tid] = g_mn_cnt[c * RR + tid];
#pragma unroll
        for (int w = 0; w < 8; w++) adjb[tid * 9 + w] = g_adjbits[tid * 8 + w];
    }
    if (tid < MAXRC) midx[tid] = g_memb_idx[c * MAXRC + tid];
    __syncthreads();
    for (int mr = warp; mr < cnt; mr += 16) {
        const float4* hp = (const float4*)(hws + mr * HW_PITCH);
        float4 x = hp[lane];
        float4 ad = ((const float4*)a1dv)[lane];
        float4 as = ((const float4*)a1sv)[lane];
        float dv = x.x * ad.x + x.y * ad.y + x.z * ad.z + x.w * ad.w;
        float sv = x.x * as.x + x.y * as.y + x.z * as.z + x.w * as.w;
#pragma unroll
        for (int o = 16; o > 0; o >>= 1) {
            dv += __shfl_xor_sync(0xffffffffu, dv, o);
            sv += __shfl_xor_sync(0xffffffffu, sv, o);
        }
        if (lane == 0) { int ridx = midx[mr]; d1s[ridx] = dv; s1s[ridx] = sv; }
    }
    __syncthreads();
    {
        int half = tid >> 8, i = tid & 255;
        float di = d1s[i];
        float dsum = 0.f;
#pragma unroll
        for (int w = half * 4; w < half * 4 + 4; w++) {
            unsigned int bits = adjb[i * 9 + w];
            while (bits) {
                int t = __ffs(bits) - 1;
                bits &= bits - 1;
                dsum += __expf(lrelu02(di + s1s[w * 32 + t]));
            }
        }
        denp[tid] = dsum;
    }
    __syncthreads();
    if (tid < 256) {
        float inv = 1.f / (denp[tid] + denp[tid + 256]);
        int mc = mcs[tid];
        float di = d1s[tid];
        const unsigned char* jr = jcs8 + tid * 16;
        for (int m = 0; m < mc; m++)
            wbufd[tid * 17 + m] = __expf(lrelu02(di + s1s[midx[jr[m]]])) * inv;
    }
    __syncthreads();
    {
        float4 bb = ((const float4*)b1v)[lane];
        float4 ad = ((const float4*)ad2)[lane];
        float4 as = ((const float4*)as2)[lane];
#pragma unroll 4
        for (int it = 0; it < 16; it++) {
            int i = it * 16 + warp;
            int mc = mcs[i];
            float4 h;
            if (mc == 0) {
                h.x = fmaxf(bb.x, 0.f); h.y = fmaxf(bb.y, 0.f);
                h.z = fmaxf(bb.z, 0.f); h.w = fmaxf(bb.w, 0.f);
            } else {
                const float* wd = wbufd + i * 17;
                const unsigned char* jr = jcs8 + i * 16;
                float4 acc = make_float4(0.f, 0.f, 0.f, 0.f);
                for (int m = 0; m < mc; m++) {
                    float w = wd[m];
                    float4 hv = *(const float4*)(hws + (int)jr[m] * HW_PITCH + 4 * lane);
                    acc.x += w * hv.x; acc.y += w * hv.y;
                    acc.z += w * hv.z; acc.w += w * hv.w;
                }
                h.x = fmaxf(acc.x + bb.x, 0.f); h.y = fmaxf(acc.y + bb.y, 0.f);
                h.z = fmaxf(acc.z + bb.z, 0.f); h.w = fmaxf(acc.w + bb.w, 0.f);
            }
            float dv = h.x * ad.x + h.y * ad.y + h.z * ad.z + h.w * ad.w;
            float sv = h.x * as.x + h.y * as.y + h.z * as.z + h.w * as.w;
#pragma unroll
            for (int o = 16; o > 0; o >>= 1) {
                dv += __shfl_xor_sync(0xffffffffu, dv, o);
                sv += __shfl_xor_sync(0xffffffffu, sv, o);
            }
            if (lane == 0) { d2s[i] = dv; s2s[i] = sv; }
        }
    }
    __syncthreads();
    {
        int half = tid >> 8, i = tid & 255;
        float di = d2s[i];
        float dsum = 0.f;
#pragma unroll
        for (int w = half * 4; w < half * 4 + 4; w++) {
            unsigned int bits = adjb[i * 9 + w];
            while (bits) {
                int t = __ffs(bits) - 1;
                bits &= bits - 1;
                dsum += __expf(lrelu02(di + s2s[w * 32 + t]));
            }
        }
        denp[tid] = dsum;
    }
    __syncthreads();
    if (tid < 256) den2[tid] = 1.f / (denp[tid] + denp[tid + 256]);
    __syncthreads();
    {
        int half = tid >> 8, j = tid & 255;
        float sj = s2s[j];
        float cs = 0.f;
#pragma unroll
        for (int w = half * 4; w < half * 4 + 4; w++) {
            unsigned int bits = adjb[j * 9 + w];
            while (bits) {
                int t = __ffs(bits) - 1;
                bits &= bits - 1;
                int i2 = w * 32 + t;
                cs += __expf(lrelu02(d2s[i2] + sj)) * den2[i2];
            }
        }
        denp[tid] = cs;
    }
    __syncthreads();
    if (tid < 256) coef[tid] = denp[tid] + denp[tid + 256];
    __syncthreads();
    {
        float4 bb = ((const float4*)b1v)[lane];
        float4 p = make_float4(0.f, 0.f, 0.f, 0.f);
#pragma unroll 4
        for (int it = 0; it < 16; it++) {
            int i = it * 16 + warp;
            int mc = mcs[i];
            float cf = coef[i];
            float4 h;
            if (mc == 0) {
                h.x = fmaxf(bb.x, 0.f); h.y = fmaxf(bb.y, 0.f);
                h.z = fmaxf(bb.z, 0.f); h.w = fmaxf(bb.w, 0.f);
            } else {
                const float* wd = wbufd + i * 17;
                const unsigned char* jr = jcs8 + i * 16;
                float4 acc = make_float4(0.f, 0.f, 0.f, 0.f);
                for (int m = 0; m < mc; m++) {
                    float w = wd[m];
                    float4 hv = *(const float4*)(hws + (int)jr[m] * HW_PITCH + 4 * lane);
                    acc.x += w * hv.x; acc.y += w * hv.y;
                    acc.z += w * hv.z; acc.w += w * hv.w;
                }
                h.x = fmaxf(acc.x + bb.x, 0.f); h.y = fmaxf(acc.y + bb.y, 0.f);
                h.z = fmaxf(acc.z + bb.z, 0.f); h.w = fmaxf(acc.w + bb.w, 0.f);
            }
            p.x += cf * h.x; p.y += cf * h.y; p.z += cf * h.z; p.w += cf * h.w;
        }
        __syncthreads();  // coef reads complete before union region becomes gpart
        ((float4*)(gpart + warp * 128))[lane] = p;
    }
    __syncthreads();
    if (tid < 128) {
        float s = 0.f;
#pragma unroll
        for (int w = 0; w < 16; w++) s += gpart[w * 128 + tid];
        gsum[tid] = s;
    }
    __syncthreads();
    if (tid < 64) {
        float acc = 0.f;
        for (int f = 0; f < 128; f++) acc += gsum[f] * W2[((size_t)c * 128 + f) * 64 + tid];
        gvec[tid] = acc + 256.f * b2[c * 64 + tid];
    }
    __syncthreads();
    if (tid < KKC) {
        float l = 0.f;
        for (int t = 0; t < 64; t++) l += gvec[t] * Wl[(c * 64 + t) * KKC + tid];
        logits[tid] = l + 256.f * bl[c * KKC + tid];
    }
    __syncthreads();
    if (tid == 0) {
        float mx = logits[0];
#pragma unroll
        for (int k = 1; k < KKC; k++) mx = fmaxf(mx, logits[k]);
        float se = 0.f;
#pragma unroll
        for (int k = 0; k < KKC; k++) se += __expf(logits[k] - mx);
        float lse = logf(se) + mx;
#pragma unroll
        for (int k = 0; k < KKC; k++) out[base * KKC + k] = logits[k] - lse;
    }
}

// ---------------- launcher ----------------
extern "C" void kernel_launch(void* const* d_in, const int* in_sizes, int n_in,
                              void* d_out, int out_size) {
    const float* vis = (const float*)d_in[0];
    const float* basic = (const float*)d_in[1];
    const float* crucial = (const float*)d_in[2];
    const float* Wtb = (const float*)d_in[3];
    const float* btb = (const float*)d_in[4];
    const float* Wtk = (const float*)d_in[5];
    const float* btk = (const float*)d_in[6];
    const float* Wq = (const float*)d_in[7];
    const float* bq = (const float*)d_in[8];
    const float* Wk = (const float*)d_in[9];
    const float* bk = (const float*)d_in[10];
    const float* Wv = (const float*)d_in[11];
    const float* bv = (const float*)d_in[12];
    const float* Wo = (const float*)d_in[13];
    const float* bo = (const float*)d_in[14];
    const float* W1 = (const float*)d_in[15];
    const float* a1s = (const float*)d_in[16];
    const float* a1d = (const float*)d_in[17];
    const float* b1 = (const float*)d_in[18];
    const float* W2 = (const float*)d_in[19];
    const float* a2s = (const float*)d_in[20];
    const float* a2d = (const float*)d_in[21];
    const float* b2 = (const float*)d_in[22];
    const float* Wl = (const float*)d_in[23];
    const float* bl = (const float*)d_in[24];
    const void* adjraw = d_in[25];
    const int* mask = (const int*)d_in[26];
    float* out = (float*)d_out;

    void *p_Kx, *p_Vx;
    cudaGetSymbolAddress(&p_Kx, g_Kx);
    cudaGetSymbolAddress(&p_Vx, g_Vx);

    cudaFuncSetAttribute((const void*)k_attn, cudaFuncAttributeMaxDynamicSharedMemorySize, ATTN_SMEM);
    cudaFuncSetAttribute((const void*)k_mega, cudaFuncAttributeMaxDynamicSharedMemorySize, MEGA_SMEM);

    // profiled slot (#4) = k_attn (R13 version)
    k_rule<<<RR, 256>>>(basic, crucial, Wtb, btb, Wtk, btk, Wq, bq);
    k_gemmKV<<<dim3(2, 128, 2), 256>>>(vis, Wk, bk, (float*)p_Kx, Wv, bv, (float*)p_Vx);
    k_sniff<<<1, 256>>>(adjraw);
    k_attn<<<dim3(4, BB), 256, ATTN_SMEM>>>();
    k_csr<<<RR, 256>>>(adjraw);
    k_memb<<<CC, 256>>>(mask);
    k_prep<<<dim3(CC, 2), 128>>>(W2, a2d, a2s, bo, W1);
    k_fusew<<<dim3(2, CC), 256>>>(Wo, W1);
    k_hw1g<<<dim3(96, CC), 256>>>();
    k_mega<<<dim3(BB, CC), 512, MEGA_SMEM>>>(a1s, a1d, b1, W2, b2, Wl, bl, out);
}

// round 16
// speedup vs baseline: 1.2614x; 1.1737x over previous
#include <cuda_runtime.h>
#include <cstdint>
#include <cstddef>

#define BB 256
#define SS 64
#define RR 256
#define VV 2000
#define CC 10
#define KKC 6
#define DD 256
#define MAXRC 48
#define MNCAP 16
#define HW_PITCH 128

typedef unsigned long long ull;

// ---------------- scratch (device globals) ----------------
__device__ float g_Q[RR * DD];
__device__ float g_Kx[BB * SS * DD];
__device__ float g_Vx[BB * SS * DD];
__device__ float g_ctx[(size_t)BB * RR * DD];
__device__ int g_adjflag;
__device__ unsigned int g_adjbits[RR * 8];
__device__ int g_nbr_cnt[RR];
__device__ int g_nbr[RR * RR];
__device__ int g_memb_cnt[CC];
__device__ int g_memb_idx[CC * MAXRC];
__device__ int g_memb_inv[CC * RR];
__device__ int g_mn_cnt[CC * RR];
__device__ unsigned char g_mn_jc8[CC * RR * MNCAP];
__device__ float g_hW1c[(size_t)CC * BB * MAXRC * 128];
__device__ float g_a2dp[CC * 128];
__device__ float g_a2sp[CC * 128];
__device__ float g_Wf[CC * DD * 128];    // Wo @ W1[c]
__device__ float g_bo1[CC * 128];        // bo @ W1[c]

__device__ __forceinline__ float lrelu02(float x) { return x > 0.f ? x : 0.2f * x; }
__device__ __forceinline__ ull pkdup(float x) { ull r; asm("mov.b64 %0,{%1,%1};" : "=l"(r) : "f"(x)); return r; }
__device__ __forceinline__ void fma2(ull& d, ull a, ull b) { asm("fma.rn.f32x2 %0,%1,%2,%0;" : "+l"(d) : "l"(a), "l"(b)); }
__device__ __forceinline__ void unpk(ull v, float& lo, float& hi) { asm("mov.b64 {%0,%1},%2;" : "=f"(lo), "=f"(hi) : "l"(v)); }
__device__ __forceinline__ float tf32f(float x) {
    unsigned u; asm("cvt.rna.tf32.f32 %0, %1;" : "=r"(u) : "f"(x));
    return __uint_as_float(u);
}
__device__ __forceinline__ void mma8(float* d, const unsigned* a, unsigned b0, unsigned b1) {
    asm volatile(
        "mma.sync.aligned.m16n8k8.row.col.f32.tf32.tf32.f32 "
        "{%0,%1,%2,%3}, {%4,%5,%6,%7}, {%8,%9}, {%0,%1,%2,%3};"
        : "+f"(d[0]), "+f"(d[1]), "+f"(d[2]), "+f"(d[3])
        : "r"(a[0]), "r"(a[1]), "r"(a[2]), "r"(a[3]), "r"(b0), "r"(b1));
}

// ---------------- adj dtype sniff ----------------
__global__ void k_sniff(const void* __restrict__ adjraw) {
    __shared__ int cntA, cntB;
    int tid = threadIdx.x;
    if (tid == 0) { cntA = 0; cntB = 0; }
    __syncthreads();
    const uint4* p = (const uint4*)adjraw;
    int a = 0, b = 0;
    for (int i = tid; i < RR * RR / 16; i += 256) {
        uint4 v = p[i];
        unsigned int w[4] = {v.x, v.y, v.z, v.w};
#pragma unroll
        for (int q = 0; q < 4; q++) {
            a += ((w[q] & 0xFFu) != 0);
            b += (((w[q] >> 8) & 0xFFu) != 0) + (((w[q] >> 16) & 0xFFu) != 0) + ((w[q] >> 24) != 0);
        }
    }
    atomicAdd(&cntA, a);
    atomicAdd(&cntB, b);
    __syncthreads();
    if (tid == 0) {
        if (cntB == 0) g_adjflag = 0;
        else if (cntA == 0) g_adjflag = 1;
        else g_adjflag = 2;
    }
}

// ---------------- adjacency CSR + bitmask via ballot ----------------
__global__ void k_csr(const void* __restrict__ adjraw) {
    __shared__ unsigned int words[8];
    __shared__ int base[8];
    const int r = blockIdx.x, tid = threadIdx.x;
    const int warp = tid >> 5, lane = tid & 31;
    const int flag = g_adjflag;
    bool nz;
    if (flag == 0) nz = ((const int*)adjraw)[r * RR + tid] != 0;
    else if (flag == 1) nz = ((const float*)adjraw)[r * RR + tid] != 0.f;
    else nz = ((const unsigned char*)adjraw)[r * RR + tid] != 0;
    unsigned int ball = __ballot_sync(0xffffffffu, nz);
    if (lane == 0) words[warp] = ball;
    __syncthreads();
    if (tid == 0) {
        int s = 0;
#pragma unroll
        for (int w = 0; w < 8; w++) { base[w] = s; s += __popc(words[w]); }
        g_nbr_cnt[r] = s;
    }
    if (tid < 8) g_adjbits[r * 8 + tid] = words[tid];
    __syncthreads();
    if (nz) {
        int pos = base[warp] + __popc(ball & ((1u << lane) - 1));
        g_nbr[r * RR + pos] = tid;
    }
}

// ---------------- per-class membership + u8 member-neighbor lists ----------------
__global__ void k_memb(const int* __restrict__ mask) {
    __shared__ unsigned int words[8];
    __shared__ int base[8];
    __shared__ int invsm[RR];
    const int c = blockIdx.x, tid = threadIdx.x;
    const int warp = tid >> 5, lane = tid & 31;
    bool mem = mask[c * RR + tid] != 0;
    unsigned int ball = __ballot_sync(0xffffffffu, mem);
    if (lane == 0) words[warp] = ball;
    __syncthreads();
    if (tid == 0) {
        int s = 0;
#pragma unroll
        for (int w = 0; w < 8; w++) { base[w] = s; s += __popc(words[w]); }
        g_memb_cnt[c] = s < MAXRC ? s : MAXRC;
    }
    __syncthreads();
    int inv = -1;
    if (mem) {
        int pos = base[warp] + __popc(ball & ((1u << lane) - 1));
        if (pos < MAXRC) { inv = pos; g_memb_idx[c * MAXRC + pos] = tid; }
    }
    invsm[tid] = inv;
    g_memb_inv[c * RR + tid] = inv;
    __syncthreads();
    int i = tid;
    int deg = g_nbr_cnt[i];
    const int* nb = g_nbr + i * RR;
    int mc = 0;
    for (int m = 0; m < deg; m++) {
        int j = nb[m];
        int jc = invsm[j];
        if (jc >= 0 && mc < MNCAP) {
            g_mn_jc8[(c * RR + i) * MNCAP + mc] = (unsigned char)jc;
            mc++;
        }
    }
    for (int m = mc; m < MNCAP; m++) g_mn_jc8[(c * RR + i) * MNCAP + m] = 0;
    g_mn_cnt[c * RR + i] = mc;
}

// ---------------- rule embedding fused with scaled Q projection ----------------
__global__ void k_rule(const float* __restrict__ basic, const float* __restrict__ crucial,
                       const float* __restrict__ Wtb, const float* __restrict__ btb,
                       const float* __restrict__ Wtk, const float* __restrict__ btk,
                       const float* __restrict__ Wq, const float* __restrict__ bq) {
    __shared__ int nzb[64], nzc[64];
    __shared__ float vb[64], vc[64];
    __shared__ int cb[256], cc2[256];
    __shared__ int totb, totc;
    __shared__ float rulesm[256];
    int r = blockIdx.x, tid = threadIdx.x;
    const float* br = basic + (size_t)r * VV;
    const float* cr = crucial + (size_t)r * VV;
    int nb = 0, nc = 0;
    int v0 = tid * 8;
#pragma unroll
    for (int t = 0; t < 8; t++) {
        int v = v0 + t;
        if (v < VV) { if (br[v] != 0.f) nb++; if (cr[v] != 0.f) nc++; }
    }
    cb[tid] = nb; cc2[tid] = nc;
    __syncthreads();
    if (tid == 0) {
        int s = 0;
        for (int i = 0; i < 256; i++) { int t = cb[i]; cb[i] = s; s += t; }
        totb = s < 64 ? s : 64;
        s = 0;
        for (int i = 0; i < 256; i++) { int t = cc2[i]; cc2[i] = s; s += t; }
        totc = s < 64 ? s : 64;
    }
    __syncthreads();
    {
        int ob = cb[tid], oc = cc2[tid];
#pragma unroll
        for (int t = 0; t < 8; t++) {
            int v = v0 + t;
            if (v < VV) {
                if (br[v] != 0.f && ob < 64) { nzb[ob] = v; vb[ob] = br[v]; ob++; }
                if (cr[v] != 0.f && oc < 64) { nzc[oc] = v; vc[oc] = cr[v]; oc++; }
            }
        }
    }
    __syncthreads();
    int d = tid;
    float acc = btb[d] + btk[d];
    int tb = totb, tc = totc;
    for (int i = 0; i < tb; i++) acc += vb[i] * Wtb[(size_t)nzb[i] * DD + d];
    for (int i = 0; i < tc; i++) acc += vc[i] * Wtk[(size_t)nzc[i] * DD + d];
    rulesm[d] = acc;
    __syncthreads();
    float q = bq[d];
#pragma unroll 4
    for (int e = 0; e < 256; e++) q += rulesm[e] * Wq[(size_t)e * DD + d];
    g_Q[(size_t)r * DD + d] = q * 0.125f;
}

// ---------------- TF32 mma GEMM, N=K=256, z-batched K/V projections ----------------
__global__ void __launch_bounds__(256, 2)
k_gemmKV(const float* __restrict__ A,
         const float* __restrict__ Wk, const float* __restrict__ bk, float* __restrict__ Kx,
         const float* __restrict__ Wv, const float* __restrict__ bv, float* __restrict__ Vx) {
    const float* W = blockIdx.z ? Wv : Wk;
    const float* bias = blockIdx.z ? bv : bk;
    float* C = blockIdx.z ? Vx : Kx;
    __shared__ float As[32][136];
    __shared__ float Bs[32][136];
    __shared__ float bsm[128];
    const int tid = threadIdx.x;
    const int row0 = blockIdx.y * 128, col0 = blockIdx.x * 128;
    const int warp = tid >> 5, lane = tid & 31;
    const int g = lane >> 2, tig = lane & 3;
    const int wr = (warp & 3) * 32, wc = (warp >> 2) * 64;
    if (tid < 128) bsm[tid] = bias[col0 + tid];
    float d[2][8][4];
#pragma unroll
    for (int rt = 0; rt < 2; rt++)
#pragma unroll
        for (int nt = 0; nt < 8; nt++)
#pragma unroll
            for (int q = 0; q < 4; q++) d[rt][nt][q] = 0.f;
    for (int k0 = 0; k0 < 256; k0 += 32) {
#pragma unroll
        for (int t = 0; t < 4; t++) {
            int idx = (tid + t * 256) * 4;
            int r = idx >> 5, kk = idx & 31;
            float4 v = *(const float4*)(A + (size_t)(row0 + r) * 256 + k0 + kk);
            As[kk][r] = tf32f(v.x); As[kk + 1][r] = tf32f(v.y);
            As[kk + 2][r] = tf32f(v.z); As[kk + 3][r] = tf32f(v.w);
        }
#pragma unroll
        for (int t = 0; t < 4; t++) {
            int idx = (tid + t * 256) * 4;
            int rk = idx >> 7, cc = idx & 127;
            float4 v = *(const float4*)(W + (size_t)(k0 + rk) * 256 + col0 + cc);
            *(float4*)&Bs[rk][cc] = make_float4(tf32f(v.x), tf32f(v.y), tf32f(v.z), tf32f(v.w));
        }
        __syncthreads();
#pragma unroll
        for (int ks = 0; ks < 32; ks += 8) {
            unsigned a[2][4];
#pragma unroll
            for (int rt = 0; rt < 2; rt++) {
                int rb = wr + rt * 16 + g;
                a[rt][0] = __float_as_uint(As[ks + tig][rb]);
                a[rt][1] = __float_as_uint(As[ks + tig][rb + 8]);
                a[rt][2] = __float_as_uint(As[ks + tig + 4][rb]);
                a[rt][3] = __float_as_uint(As[ks + tig + 4][rb + 8]);
            }
#pragma unroll
            for (int nt = 0; nt < 8; nt++) {
                int nb = wc + nt * 8 + g;
                unsigned b0 = __float_as_uint(Bs[ks + tig][nb]);
                unsigned b1 = __float_as_uint(Bs[ks + tig + 4][nb]);
                mma8(d[0][nt], a[0], b0, b1);
                mma8(d[1][nt], a[1], b0, b1);
            }
        }
        __syncthreads();
    }
#pragma unroll
    for (int rt = 0; rt < 2; rt++) {
        int r = row0 + wr + rt * 16 + g;
#pragma unroll
        for (int nt = 0; nt < 8; nt++) {
            int ccol = wc + nt * 8 + tig * 2;
            float bv0 = bsm[ccol], bv1 = bsm[ccol + 1];
            float2 v0 = make_float2(d[rt][nt][0] + bv0, d[rt][nt][1] + bv1);
            float2 v1 = make_float2(d[rt][nt][2] + bv0, d[rt][nt][3] + bv1);
            *(float2*)(C + (size_t)r * 256 + col0 + ccol) = v0;
            *(float2*)(C + (size_t)(r + 8) * 256 + col0 + ccol) = v1;
        }
    }
}

// ---------------- register-tiled cross-attention per (h, b) [R13 winner] ----------------
#define QT_PITCH 260
#define PT_PITCH 264
#define KV_PITCH 74
#define AT_KT (64 * PT_PITCH)
#define AT_V (AT_KT + 64 * KV_PITCH)
#define ATTN_SMEM ((AT_V + 64 * KV_PITCH) * 4)
__global__ void __launch_bounds__(256, 2) k_attn() {
    extern __shared__ float sm[];
    float* QP = sm;
    float* Kt = sm + AT_KT;
    float* Vs = sm + AT_V;
    const int tid = threadIdx.x;
    const int h = blockIdx.x, b = blockIdx.y;
    for (int idx = tid; idx < 256 * 64; idx += 256) {
        int k = idx & 63, r = idx >> 6;
        QP[k * QT_PITCH + r] = g_Q[(size_t)r * DD + h * 64 + k];
    }
    for (int idx = tid; idx < 64 * 64; idx += 256) {
        int k = idx & 63, s = idx >> 6;
        Kt[k * KV_PITCH + s] = g_Kx[(size_t)(b * SS + s) * DD + h * 64 + k];
        Vs[s * KV_PITCH + k] = g_Vx[(size_t)(b * SS + s) * DD + h * 64 + k];
    }
    __syncthreads();
    const int trow = tid >> 3, tcol = tid & 7;
    const int rbase = trow * 8, sbase = tcol * 8;
    ull acc[8][4];
#pragma unroll
    for (int r = 0; r < 8; r++)
#pragma unroll
        for (int j = 0; j < 4; j++) acc[r][j] = 0ull;
    for (int k = 0; k < 64; k++) {
        const float4* qr = (const float4*)(QP + k * QT_PITCH + rbase);
        float4 qa = qr[0], qb = qr[1];
        const ull* kp = (const ull*)(Kt + k * KV_PITCH + sbase);
        ull b0 = kp[0], b1 = kp[1], b2 = kp[2], b3 = kp[3];
        float qs[8] = {qa.x, qa.y, qa.z, qa.w, qb.x, qb.y, qb.z, qb.w};
#pragma unroll
        for (int r = 0; r < 8; r++) {
            ull qd = pkdup(qs[r]);
            fma2(acc[r][0], qd, b0);
            fma2(acc[r][1], qd, b1);
            fma2(acc[r][2], qd, b2);
            fma2(acc[r][3], qd, b3);
        }
    }
    float p[8][8];
#pragma unroll
    for (int r = 0; r < 8; r++) {
#pragma unroll
        for (int j = 0; j < 4; j++) unpk(acc[r][j], p[r][2 * j], p[r][2 * j + 1]);
        float m = p[r][0];
#pragma unroll
        for (int j = 1; j < 8; j++) m = fmaxf(m, p[r][j]);
        m = fmaxf(m, __shfl_xor_sync(0xffffffffu, m, 1));
        m = fmaxf(m, __shfl_xor_sync(0xffffffffu, m, 2));
        m = fmaxf(m, __shfl_xor_sync(0xffffffffu, m, 4));
        float sum = 0.f;
#pragma unroll
        for (int j = 0; j < 8; j++) { p[r][j] = __expf(p[r][j] - m); sum += p[r][j]; }
        sum += __shfl_xor_sync(0xffffffffu, sum, 1);
        sum += __shfl_xor_sync(0xffffffffu, sum, 2);
        sum += __shfl_xor_sync(0xffffffffu, sum, 4);
        float inv = 1.f / sum;
#pragma unroll
        for (int j = 0; j < 8; j++) p[r][j] *= inv;
    }
    __syncthreads();
#pragma unroll
    for (int i = 0; i < 8; i++) {
        float* dst = QP + (sbase + i) * PT_PITCH + rbase;
        *(float4*)dst = make_float4(p[0][i], p[1][i], p[2][i], p[3][i]);
        *(float4*)(dst + 4) = make_float4(p[4][i], p[5][i], p[6][i], p[7][i]);
    }
    __syncthreads();
    ull c2[8][4];
#pragma unroll
    for (int r = 0; r < 8; r++)
#pragma unroll
        for (int j = 0; j < 4; j++) c2[r][j] = 0ull;
    for (int s = 0; s < 64; s++) {
        const float* pr = QP + s * PT_PITCH + rbase;
        float4 pa = *(const float4*)pr;
        float4 pb = *(const float4*)(pr + 4);
        const ull* vp = (const ull*)(Vs + s * KV_PITCH + sbase);
        ull v0 = vp[0], v1 = vp[1], v2 = vp[2], v3 = vp[3];
        float pv[8] = {pa.x, pa.y, pa.z, pa.w, pb.x, pb.y, pb.z, pb.w};
#pragma unroll
        for (int r = 0; r < 8; r++) {
            ull pd = pkdup(pv[r]);
            fma2(c2[r][0], pd, v0);
            fma2(c2[r][1], pd, v1);
            fma2(c2[r][2], pd, v2);
            fma2(c2[r][3], pd, v3);
        }
    }
#pragma unroll
    for (int r = 0; r < 8; r++) {
        float o[8];
#pragma unroll
        for (int j = 0; j < 4; j++) unpk(c2[r][j], o[2 * j], o[2 * j + 1]);
        float* op = g_ctx + (size_t)(b * RR + rbase + r) * DD + h * 64 + sbase;
        *(float4*)op = make_float4(o[0], o[1], o[2], o[3]);
        *(float4*)(op + 4) = make_float4(o[4], o[5], o[6], o[7]);
    }
}

// ---------------- gathered per-class GEMM (TF32 mma) ----------------
__global__ void __launch_bounds__(256, 2)
k_hw1g() {
    const int c = blockIdx.y;
    const int cnt = g_memb_cnt[c];
    const int Mc = BB * cnt;
    const int row0 = blockIdx.x * 128;
    if (row0 >= Mc) return;
    __shared__ float As[32][136];
    __shared__ float Bs[32][136];
    __shared__ float bsm[128];
    __shared__ int rowbase[128];
    __shared__ int outbase[128];
    const int tid = threadIdx.x;
    const int warp = tid >> 5, lane = tid & 31;
    const int g = lane >> 2, tig = lane & 3;
    const int wr = (warp & 3) * 32, wc = (warp >> 2) * 64;
    if (tid < 128) {
        bsm[tid] = g_bo1[c * 128 + tid];
        int gg = row0 + tid;
        if (gg < Mc) {
            int b = gg / cnt, mr = gg - b * cnt;
            int ridx = g_memb_idx[c * MAXRC + mr];
            rowbase[tid] = (b * RR + ridx) * DD;
            outbase[tid] = ((c * BB + b) * MAXRC + mr) * 128;
        } else { rowbase[tid] = 0; outbase[tid] = -1; }
    }
    __syncthreads();
    const float* Wc = g_Wf + (size_t)c * DD * 128;
    float d[2][8][4];
#pragma unroll
    for (int rt = 0; rt < 2; rt++)
#pragma unroll
        for (int nt = 0; nt < 8; nt++)
#pragma unroll
            for (int q = 0; q < 4; q++) d[rt][nt][q] = 0.f;
    for (int k0 = 0; k0 < 256; k0 += 32) {
#pragma unroll
        for (int t = 0; t < 4; t++) {
            int idx = (tid + t * 256) * 4;
            int r = idx >> 5, kk = idx & 31;
            float4 v = *(const float4*)(g_ctx + (size_t)rowbase[r] + k0 + kk);
            As[kk][r] = tf32f(v.x); As[kk + 1][r] = tf32f(v.y);
            As[kk + 2][r] = tf32f(v.z); As[kk + 3][r] = tf32f(v.w);
        }
#pragma unroll
        for (int t = 0; t < 4; t++) {
            int idx = (tid + t * 256) * 4;
            int rk = idx >> 7, cc = idx & 127;
            float4 v = *(const float4*)(Wc + (size_t)(k0 + rk) * 128 + cc);
            *(float4*)&Bs[rk][cc] = make_float4(tf32f(v.x), tf32f(v.y), tf32f(v.z), tf32f(v.w));
        }
        __syncthreads();
#pragma unroll
        for (int ks = 0; ks < 32; ks += 8) {
            unsigned a[2][4];
#pragma unroll
            for (int rt = 0; rt < 2; rt++) {
                int rb = wr + rt * 16 + g;
                a[rt][0] = __float_as_uint(As[ks + tig][rb]);
                a[rt][1] = __float_as_uint(As[ks + tig][rb + 8]);
                a[rt][2] = __float_as_uint(As[ks + tig + 4][rb]);
                a[rt][3] = __float_as_uint(As[ks + tig + 4][rb + 8]);
            }
#pragma unroll
            for (int nt = 0; nt < 8; nt++) {
                int nb = wc + nt * 8 + g;
                unsigned b0 = __float_as_uint(Bs[ks + tig][nb]);
                unsigned b1 = __float_as_uint(Bs[ks + tig + 4][nb]);
                mma8(d[0][nt], a[0], b0, b1);
                mma8(d[1][nt], a[1], b0, b1);
            }
        }
        __syncthreads();
    }
#pragma unroll
    for (int rt = 0; rt < 2; rt++) {
        int lr = wr + rt * 16 + g;
        int ob0 = outbase[lr], ob1 = outbase[lr + 8];
#pragma unroll
        for (int nt = 0; nt < 8; nt++) {
            int ccol = wc + nt * 8 + tig * 2;
            float bv0 = bsm[ccol], bv1 = bsm[ccol + 1];
            if (ob0 >= 0)
                *(float2*)(g_hW1c + (size_t)ob0 + ccol) =
                    make_float2(d[rt][nt][0] + bv0, d[rt][nt][1] + bv1);
            if (ob1 >= 0)
                *(float2*)(g_hW1c + (size_t)ob1 + ccol) =
                    make_float2(d[rt][nt][2] + bv0, d[rt][nt][3] + bv1);
        }
    }
}

// ---------------- Wf[c] = Wo @ W1[c]  (fp32, unchanged) ----------------
__global__ void __launch_bounds__(256, 2)
k_fusew(const float* __restrict__ Wo, const float* __restrict__ W1) {
    const int c = blockIdx.y;
    const int row0 = blockIdx.x * 128;
    __shared__ float As[32][130];
    __shared__ float Bs[32][128];
    const int tid = threadIdx.x;
    const float* Wc = W1 + (size_t)c * DD * 128;
    const int trow = tid >> 4, tcol = tid & 15;
    ull acc[4][8];
#pragma unroll
    for (int p = 0; p < 4; p++)
#pragma unroll
        for (int j = 0; j < 8; j++) acc[p][j] = 0ull;
    for (int k0 = 0; k0 < 256; k0 += 32) {
#pragma unroll
        for (int t = 0; t < 4; t++) {
            int idx = (tid + t * 256) * 4;
            int r = idx >> 5, kk = idx & 31;
            float4 v = *(const float4*)(Wo + (size_t)(row0 + r) * 256 + k0 + kk);
            As[kk][r] = v.x; As[kk + 1][r] = v.y; As[kk + 2][r] = v.z; As[kk + 3][r] = v.w;
        }
#pragma unroll
        for (int t = 0; t < 4; t++) {
            int idx = (tid + t * 256) * 4;
            int rk = idx >> 7, cc = idx & 127;
            *(float4*)&Bs[rk][cc] = *(const float4*)(Wc + (size_t)(k0 + rk) * 128 + cc);
        }
        __syncthreads();
#pragma unroll
        for (int k = 0; k < 32; k++) {
            ull a2[4], b2[8];
#pragma unroll
            for (int p = 0; p < 4; p++) a2[p] = *(const ull*)&As[k][trow * 8 + 2 * p];
#pragma unroll
            for (int j = 0; j < 8; j++) b2[j] = pkdup(Bs[k][tcol + 16 * j]);
#pragma unroll
            for (int p = 0; p < 4; p++)
#pragma unroll
                for (int j = 0; j < 8; j++) fma2(acc[p][j], a2[p], b2[j]);
        }
        __syncthreads();
    }
    float* Cc = g_Wf + (size_t)c * DD * 128;
#pragma unroll
    for (int p = 0; p < 4; p++) {
        float* C0 = Cc + (size_t)(row0 + trow * 8 + 2 * p) * 128;
        float* C1 = C0 + 128;
#pragma unroll
        for (int j = 0; j < 8; j++) {
            float lo, hi;
            unpk(acc[p][j], lo, hi);
            int cc = tcol + 16 * j;
            C0[cc] = lo;
            C1[cc] = hi;
        }
    }
}

// ---------------- fused prep: y==0 -> a2 projections; y==1 -> bo1 ----------------
__global__ void k_prep(const float* __restrict__ W2, const float* __restrict__ a2d,
                       const float* __restrict__ a2s, const float* __restrict__ bo,
                       const float* __restrict__ W1) {
    int c = blockIdx.x, f = threadIdx.x;
    if (blockIdx.y == 0) {
        float dv = 0.f, sv = 0.f;
        const float* wr = W2 + ((size_t)c * 128 + f) * 64;
#pragma unroll
        for (int g = 0; g < 64; g++) {
            float w = wr[g];
            dv += w * a2d[c * 64 + g];
            sv += w * a2s[c * 64 + g];
        }
        g_a2dp[c * 128 + f] = dv;
        g_a2sp[c * 128 + f] = sv;
    } else {
        const float* Wc = W1 + (size_t)c * DD * 128;
        float acc = 0.f;
        for (int e = 0; e < DD; e++) acc += bo[e] * Wc[(size_t)e * 128 + f];
        g_bo1[c * 128 + f] = acc;
    }
}

// ---------------- fused GAT stack v5 (unchanged) ----------------
#define MG_HWS 0
#define MG_WBUF 6144
#define MG_UNION 10496
#define MG_A1D 12544
#define MG_A1S 12672
#define MG_B1 12800
#define MG_AD2 12928
#define MG_AS2 13056
#define MG_D1 13184
#define MG_S1 13440
#define MG_DEN1 13696
#define MG_D2 13952
#define MG_S2 14208
#define MG_DEN2 14464
#define MG_COEF 14720
#define MG_GSUM 14976
#define MG_GVEC 15104
#define MG_LOG 15168
#define MG_MCS 15176
#define MG_MIDX 15432
#define MG_ADJB 15496
#define MG_JCS8 17800
#define MEGA_SMEM (18824 * 4)
__global__ void __launch_bounds__(512, 3)
k_mega(const float* __restrict__ a1s, const float* __restrict__ a1d,
       const float* __restrict__ b1, const float* __restrict__ W2,
       const float* __restrict__ b2, const float* __restrict__ Wl,
       const float* __restrict__ bl, float* __restrict__ out) {
    extern __shared__ float sm[];
    float* hws = sm + MG_HWS;
    float* wbufd = sm + MG_WBUF;
    float* denp = sm + MG_UNION;
    float* gpart = sm + MG_UNION;
    float* a1dv = sm + MG_A1D;
    float* a1sv = sm + MG_A1S;
    float* b1v = sm + MG_B1;
    float* ad2 = sm + MG_AD2;
    float* as2 = sm + MG_AS2;
    float* d1s = sm + MG_D1;
    float* s1s = sm + MG_S1;
    float* den1 = sm + MG_DEN1;
    float* d2s = sm + MG_D2;
    float* s2s = sm + MG_S2;
    float* den2 = sm + MG_DEN2;
    float* coef = sm + MG_COEF;
    float* gsum = sm + MG_GSUM;
    float* gvec = sm + MG_GVEC;
    float* logits = sm + MG_LOG;
    int* mcs = (int*)(sm + MG_MCS);
    int* midx = (int*)(sm + MG_MIDX);
    unsigned int* adjb = (unsigned int*)(sm + MG_ADJB);
    unsigned char* jcs8 = (unsigned char*)(sm + MG_JCS8);
    const int b = blockIdx.x, c = blockIdx.y, tid = threadIdx.x;
    const int warp = tid >> 5, lane = tid & 31;
    const int cnt = g_memb_cnt[c];
    const size_t base = (size_t)(c * BB + b);
    {
        const float4* src4 = (const float4*)(g_hW1c + base * MAXRC * 128);
        float4* dst4 = (float4*)hws;
        int n4 = cnt * 32;
        for (int i = tid; i < n4; i += 512) dst4[i] = src4[i];
    }
    {
        unsigned int* j32 = (unsigned int*)jcs8;
        const unsigned int* gsrc = (const unsigned int*)g_mn_jc8 + c * RR * MNCAP / 4;
        for (int i = tid; i < RR * MNCAP / 4; i += 512) j32[i] = gsrc[i];
    }
    if (tid < 128) {
        a1dv[tid] = a1d[c * 128 + tid];
        a1sv[tid] = a1s[c * 128 + tid];
        b1v[tid] = b1[c * 128 + tid];
        ad2[tid] = g_a2dp[c * 128 + tid];
        as2[tid] = g_a2sp[c * 128 + tid];
    }
    if (tid < 256) {
        d1s[tid] = 0.f; s1s[tid] = 0.f;
        mcs[tid] = g_mn_cnt[c * RR + tid];
#pragma unroll
        for (int w = 0; w < 8; w++) adjb[tid * 9 + w] = g_adjbits[tid * 8 + w];
    }
    if (tid < MAXRC) midx[tid] = g_memb_idx[c * MAXRC + tid];
    __syncthreads();
    for (int mr = warp; mr < cnt; mr += 16) {
        const float4* hp = (const float4*)(hws + mr * HW_PITCH);
        float4 x = hp[lane];
        float4 ad = ((const float4*)a1dv)[lane];
        float4 as = ((const float4*)a1sv)[lane];
        float dv = x.x * ad.x + x.y * ad.y + x.z * ad.z + x.w * ad.w;
        float sv = x.x * as.x + x.y * as.y + x.z * as.z + x.w * as.w;
#pragma unroll
        for (int o = 16; o > 0; o >>= 1) {
            dv += __shfl_xor_sync(0xffffffffu, dv, o);
            sv += __shfl_xor_sync(0xffffffffu, sv, o);
        }
        if (lane == 0) { int ridx = midx[mr]; d1s[ridx] = dv; s1s[ridx] = sv; }
    }
    __syncthreads();
    {
        int half = tid >> 8, i = tid & 255;
        float di = d1s[i];
        float dsum = 0.f;
#pragma unroll
        for (int w = half * 4; w < half * 4 + 4; w++) {
            unsigned int bits = adjb[i * 9 + w];
            while (bits) {
                int t = __ffs(bits) - 1;
                bits &= bits - 1;
                dsum += __expf(lrelu02(di + s1s[w * 32 + t]));
            }
        }
        denp[tid] = dsum;
    }
    __syncthreads();
    if (tid < 256) {
        float inv = 1.f / (denp[tid] + denp[tid + 256]);
        int mc = mcs[tid];
        float di = d1s[tid];
        const unsigned char* jr = jcs8 + tid * 16;
        for (int m = 0; m < mc; m++)
            wbufd[tid * 17 + m] = __expf(lrelu02(di + s1s[midx[jr[m]]])) * inv;
    }
    __syncthreads();
    {
        float4 bb = ((const float4*)b1v)[lane];
        float4 ad = ((const float4*)ad2)[lane];
        float4 as = ((const float4*)as2)[lane];
#pragma unroll 4
        for (int it = 0; it < 16; it++) {
            int i = it * 16 + warp;
            int mc = mcs[i];
            float4 h;
            if (mc == 0) {
                h.x = fmaxf(bb.x, 0.f); h.y = fmaxf(bb.y, 0.f);
                h.z = fmaxf(bb.z, 0.f); h.w = fmaxf(bb.w, 0.f);
            } else {
                const float* wd = wbufd + i * 17;
                const unsigned char* jr = jcs8 + i * 16;
                float4 acc = make_float4(0.f, 0.f, 0.f, 0.f);
                for (int m = 0; m < mc; m++) {
                    float w = wd[m];
                    float4 hv = *(const float4*)(hws + (int)jr[m] * HW_PITCH + 4 * lane);
                    acc.x += w * hv.x; acc.y += w * hv.y;
                    acc.z += w * hv.z; acc.w += w * hv.w;
                }
                h.x = fmaxf(acc.x + bb.x, 0.f); h.y = fmaxf(acc.y + bb.y, 0.f);
                h.z = fmaxf(acc.z + bb.z, 0.f); h.w = fmaxf(acc.w + bb.w, 0.f);
            }
            float dv = h.x * ad.x + h.y * ad.y + h.z * ad.z + h.w * ad.w;
            float sv = h.x * as.x + h.y * as.y + h.z * as.z + h.w * as.w;
#pragma unroll
            for (int o = 16; o > 0; o >>= 1) {
                dv += __shfl_xor_sync(0xffffffffu, dv, o);
                sv += __shfl_xor_sync(0xffffffffu, sv, o);
            }
            if (lane == 0) { d2s[i] = dv; s2s[i] = sv; }
        }
    }
    __syncthreads();
    {
        int half = tid >> 8, i = tid & 255;
        float di = d2s[i];
        float dsum = 0.f;
#pragma unroll
        for (int w = half * 4; w < half * 4 + 4; w++) {
            unsigned int bits = adjb[i * 9 + w];
            while (bits) {
                int t = __ffs(bits) - 1;
                bits &= bits - 1;
                dsum += __expf(lrelu02(di + s2s[w * 32 + t]));
            }
        }
        denp[tid] = dsum;
    }
    __syncthreads();
    if (tid < 256) den2[tid] = 1.f / (denp[tid] + denp[tid + 256]);
    __syncthreads();
    {
        int half = tid >> 8, j = tid & 255;
        float sj = s2s[j];
        float cs = 0.f;
#pragma unroll
        for (int w = half * 4; w < half * 4 + 4; w++) {
            unsigned int bits = adjb[j * 9 + w];
            while (bits) {
                int t = __ffs(bits) - 1;
                bits &= bits - 1;
                int i2 = w * 32 + t;
                cs += __expf(lrelu02(d2s[i2] + sj)) * den2[i2];
            }
        }
        denp[tid] = cs;
    }
    __syncthreads();
    if (tid < 256) coef[tid] = denp[tid] + denp[tid + 256];
    __syncthreads();
    {
        float4 bb = ((const float4*)b1v)[lane];
        float4 p = make_float4(0.f, 0.f, 0.f, 0.f);
#pragma unroll 4
        for (int it = 0; it < 16; it++) {
            int i = it * 16 + warp;
            int mc = mcs[i];
            float cf = coef[i];
            float4 h;
            if (mc == 0) {
                h.x = fmaxf(bb.x, 0.f); h.y = fmaxf(bb.y, 0.f);
                h.z = fmaxf(bb.z, 0.f); h.w = fmaxf(bb.w, 0.f);
            } else {
                const float* wd = wbufd + i * 17;
                const unsigned char* jr = jcs8 + i * 16;
                float4 acc = make_float4(0.f, 0.f, 0.f, 0.f);
                for (int m = 0; m < mc; m++) {
                    float w = wd[m];
                    float4 hv = *(const float4*)(hws + (int)jr[m] * HW_PITCH + 4 * lane);
                    acc.x += w * hv.x; acc.y += w * hv.y;
                    acc.z += w * hv.z; acc.w += w * hv.w;
                }
                h.x = fmaxf(acc.x + bb.x, 0.f); h.y = fmaxf(acc.y + bb.y, 0.f);
                h.z = fmaxf(acc.z + bb.z, 0.f); h.w = fmaxf(acc.w + bb.w, 0.f);
            }
            p.x += cf * h.x; p.y += cf * h.y; p.z += cf * h.z; p.w += cf * h.w;
        }
        __syncthreads();
        ((float4*)(gpart + warp * 128))[lane] = p;
    }
    __syncthreads();
    if (tid < 128) {
        float s = 0.f;
#pragma unroll
        for (int w = 0; w < 16; w++) s += gpart[w * 128 + tid];
        gsum[tid] = s;
    }
    __syncthreads();
    if (tid < 64) {
        float acc = 0.f;
        for (int f = 0; f < 128; f++) acc += gsum[f] * W2[((size_t)c * 128 + f) * 64 + tid];
        gvec[tid] = acc + 256.f * b2[c * 64 + tid];
    }
    __syncthreads();
    if (tid < KKC) {
        float l = 0.f;
        for (int t = 0; t < 64; t++) l += gvec[t] * Wl[(c * 64 + t) * KKC + tid];
        logits[tid] = l + 256.f * bl[c * KKC + tid];
    }
    __syncthreads();
    if (tid == 0) {
        float mx = logits[0];
#pragma unroll
        for (int k = 1; k < KKC; k++) mx = fmaxf(mx, logits[k]);
        float se = 0.f;
#pragma unroll
        for (int k = 0; k < KKC; k++) se += __expf(logits[k] - mx);
        float lse = logf(se) + mx;
#pragma unroll
        for (int k = 0; k < KKC; k++) out[base * KKC + k] = logits[k] - lse;
    }
}

// ---------------- launcher ----------------
extern "C" void kernel_launch(void* const* d_in, const int* in_sizes, int n_in,
                              void* d_out, int out_size) {
    const float* vis = (const float*)d_in[0];
    const float* basic = (const float*)d_in[1];
    const float* crucial = (const float*)d_in[2];
    const float* Wtb = (const float*)d_in[3];
    const float* btb = (const float*)d_in[4];
    const float* Wtk = (const float*)d_in[5];
    const float* btk = (const float*)d_in[6];
    const float* Wq = (const float*)d_in[7];
    const float* bq = (const float*)d_in[8];
    const float* Wk = (const float*)d_in[9];
    const float* bk = (const float*)d_in[10];
    const float* Wv = (const float*)d_in[11];
    const float* bv = (const float*)d_in[12];
    const float* Wo = (const float*)d_in[13];
    const float* bo = (const float*)d_in[14];
    const float* W1 = (const float*)d_in[15];
    const float* a1s = (const float*)d_in[16];
    const float* a1d = (const float*)d_in[17];
    const float* b1 = (const float*)d_in[18];
    const float* W2 = (const float*)d_in[19];
    const float* a2s = (const float*)d_in[20];
    const float* a2d = (const float*)d_in[21];
    const float* b2 = (const float*)d_in[22];
    const float* Wl = (const float*)d_in[23];
    const float* bl = (const float*)d_in[24];
    const void* adjraw = d_in[25];
    const int* mask = (const int*)d_in[26];
    float* out = (float*)d_out;

    void *p_Kx, *p_Vx;
    cudaGetSymbolAddress(&p_Kx, g_Kx);
    cudaGetSymbolAddress(&p_Vx, g_Vx);

    cudaFuncSetAttribute((const void*)k_attn, cudaFuncAttributeMaxDynamicSharedMemorySize, ATTN_SMEM);
    cudaFuncSetAttribute((const void*)k_mega, cudaFuncAttributeMaxDynamicSharedMemorySize, MEGA_SMEM);

    // profiled slot (#4) = k_attn
    k_rule<<<RR, 256>>>(basic, crucial, Wtb, btb, Wtk, btk, Wq, bq);
    k_gemmKV<<<dim3(2, 128, 2), 256>>>(vis, Wk, bk, (float*)p_Kx, Wv, bv, (float*)p_Vx);
    k_sniff<<<1, 256>>>(adjraw);
    k_attn<<<dim3(4, BB), 256, ATTN_SMEM>>>();
    k_csr<<<RR, 256>>>(adjraw);
    k_memb<<<CC, 256>>>(mask);
    k_prep<<<dim3(CC, 2), 128>>>(W2, a2d, a2s, bo, W1);
    k_fusew<<<dim3(2, CC), 256>>>(Wo, W1);
    k_hw1g<<<dim3(96, CC), 256>>>();
    k_mega<<<dim3(BB, CC), 512, MEGA_SMEM>>>(a1s, a1d, b1, W2, b2, Wl, bl, out);
}

// round 17
// speedup vs baseline: 1.3885x; 1.1007x over previous
#include <cuda_runtime.h>
#include <cstdint>
#include <cstddef>

#define BB 256
#define SS 64
#define RR 256
#define VV 2000
#define CC 10
#define KKC 6
#define DD 256
#define MAXRC 48
#define MNCAP 16
#define HW_PITCH 128

typedef unsigned long long ull;

// ---------------- scratch (device globals) ----------------
__device__ float g_Q[RR * DD];
__device__ float g_Kx[BB * SS * DD];
__device__ float g_Vx[BB * SS * DD];
__device__ float g_ctx[(size_t)BB * RR * DD];
__device__ int g_adjflag;
__device__ unsigned int g_adjbits[RR * 8];
__device__ int g_nbr_cnt[RR];
__device__ int g_nbr[RR * RR];
__device__ int g_memb_cnt[CC];
__device__ int g_memb_idx[CC * MAXRC];
__device__ int g_memb_inv[CC * RR];
__device__ int g_mn_cnt[CC * RR];
__device__ unsigned char g_mn_jc8[CC * RR * MNCAP];
__device__ float g_hW1c[(size_t)CC * BB * MAXRC * 128];
__device__ float g_a2dp[CC * 128];
__device__ float g_a2sp[CC * 128];
__device__ float g_Wf[CC * DD * 128];    // Wo @ W1[c]
__device__ float g_bo1[CC * 128];        // bo @ W1[c]

__device__ __forceinline__ float lrelu02(float x) { return x > 0.f ? x : 0.2f * x; }
__device__ __forceinline__ ull pkdup(float x) { ull r; asm("mov.b64 %0,{%1,%1};" : "=l"(r) : "f"(x)); return r; }
__device__ __forceinline__ void fma2(ull& d, ull a, ull b) { asm("fma.rn.f32x2 %0,%1,%2,%0;" : "+l"(d) : "l"(a), "l"(b)); }
__device__ __forceinline__ void unpk(ull v, float& lo, float& hi) { asm("mov.b64 {%0,%1},%2;" : "=f"(lo), "=f"(hi) : "l"(v)); }
__device__ __forceinline__ float tf32f(float x) {
    unsigned u; asm("cvt.rna.tf32.f32 %0, %1;" : "=r"(u) : "f"(x));
    return __uint_as_float(u);
}
__device__ __forceinline__ void mma8(float* d, const unsigned* a, unsigned b0, unsigned b1) {
    asm volatile(
        "mma.sync.aligned.m16n8k8.row.col.f32.tf32.tf32.f32 "
        "{%0,%1,%2,%3}, {%4,%5,%6,%7}, {%8,%9}, {%0,%1,%2,%3};"
        : "+f"(d[0]), "+f"(d[1]), "+f"(d[2]), "+f"(d[3])
        : "r"(a[0]), "r"(a[1]), "r"(a[2]), "r"(a[3]), "r"(b0), "r"(b1));
}

// ---------------- adj dtype sniff ----------------
__global__ void k_sniff(const void* __restrict__ adjraw) {
    __shared__ int cntA, cntB;
    int tid = threadIdx.x;
    if (tid == 0) { cntA = 0; cntB = 0; }
    __syncthreads();
    const uint4* p = (const uint4*)adjraw;
    int a = 0, b = 0;
    for (int i = tid; i < RR * RR / 16; i += 256) {
        uint4 v = p[i];
        unsigned int w[4] = {v.x, v.y, v.z, v.w};
#pragma unroll
        for (int q = 0; q < 4; q++) {
            a += ((w[q] & 0xFFu) != 0);
            b += (((w[q] >> 8) & 0xFFu) != 0) + (((w[q] >> 16) & 0xFFu) != 0) + ((w[q] >> 24) != 0);
        }
    }
    atomicAdd(&cntA, a);
    atomicAdd(&cntB, b);
    __syncthreads();
    if (tid == 0) {
        if (cntB == 0) g_adjflag = 0;
        else if (cntA == 0) g_adjflag = 1;
        else g_adjflag = 2;
    }
}

// ---------------- adjacency CSR + bitmask via ballot ----------------
__global__ void k_csr(const void* __restrict__ adjraw) {
    __shared__ unsigned int words[8];
    __shared__ int base[8];
    const int r = blockIdx.x, tid = threadIdx.x;
    const int warp = tid >> 5, lane = tid & 31;
    const int flag = g_adjflag;
    bool nz;
    if (flag == 0) nz = ((const int*)adjraw)[r * RR + tid] != 0;
    else if (flag == 1) nz = ((const float*)adjraw)[r * RR + tid] != 0.f;
    else nz = ((const unsigned char*)adjraw)[r * RR + tid] != 0;
    unsigned int ball = __ballot_sync(0xffffffffu, nz);
    if (lane == 0) words[warp] = ball;
    __syncthreads();
    if (tid == 0) {
        int s = 0;
#pragma unroll
        for (int w = 0; w < 8; w++) { base[w] = s; s += __popc(words[w]); }
        g_nbr_cnt[r] = s;
    }
    if (tid < 8) g_adjbits[r * 8 + tid] = words[tid];
    __syncthreads();
    if (nz) {
        int pos = base[warp] + __popc(ball & ((1u << lane) - 1));
        g_nbr[r * RR + pos] = tid;
    }
}

// ---------------- per-class membership + u8 member-neighbor lists ----------------
__global__ void k_memb(const int* __restrict__ mask) {
    __shared__ unsigned int words[8];
    __shared__ int base[8];
    __shared__ int invsm[RR];
    const int c = blockIdx.x, tid = threadIdx.x;
    const int warp = tid >> 5, lane = tid & 31;
    bool mem = mask[c * RR + tid] != 0;
    unsigned int ball = __ballot_sync(0xffffffffu, mem);
    if (lane == 0) words[warp] = ball;
    __syncthreads();
    if (tid == 0) {
        int s = 0;
#pragma unroll
        for (int w = 0; w < 8; w++) { base[w] = s; s += __popc(words[w]); }
        g_memb_cnt[c] = s < MAXRC ? s : MAXRC;
    }
    __syncthreads();
    int inv = -1;
    if (mem) {
        int pos = base[warp] + __popc(ball & ((1u << lane) - 1));
        if (pos < MAXRC) { inv = pos; g_memb_idx[c * MAXRC + pos] = tid; }
    }
    invsm[tid] = inv;
    g_memb_inv[c * RR + tid] = inv;
    __syncthreads();
    int i = tid;
    int deg = g_nbr_cnt[i];
    const int* nb = g_nbr + i * RR;
    int mc = 0;
    for (int m = 0; m < deg; m++) {
        int j = nb[m];
        int jc = invsm[j];
        if (jc >= 0 && mc < MNCAP) {
            g_mn_jc8[(c * RR + i) * MNCAP + mc] = (unsigned char)jc;
            mc++;
        }
    }
    for (int m = mc; m < MNCAP; m++) g_mn_jc8[(c * RR + i) * MNCAP + m] = 0;
    g_mn_cnt[c * RR + i] = mc;
}

// ---------------- rule embedding fused with scaled Q projection ----------------
__global__ void k_rule(const float* __restrict__ basic, const float* __restrict__ crucial,
                       const float* __restrict__ Wtb, const float* __restrict__ btb,
                       const float* __restrict__ Wtk, const float* __restrict__ btk,
                       const float* __restrict__ Wq, const float* __restrict__ bq) {
    __shared__ int nzb[64], nzc[64];
    __shared__ float vb[64], vc[64];
    __shared__ int cb[256], cc2[256];
    __shared__ int totb, totc;
    __shared__ float rulesm[256];
    int r = blockIdx.x, tid = threadIdx.x;
    const float* br = basic + (size_t)r * VV;
    const float* cr = crucial + (size_t)r * VV;
    int nb = 0, nc = 0;
    int v0 = tid * 8;
#pragma unroll
    for (int t = 0; t < 8; t++) {
        int v = v0 + t;
        if (v < VV) { if (br[v] != 0.f) nb++; if (cr[v] != 0.f) nc++; }
    }
    cb[tid] = nb; cc2[tid] = nc;
    __syncthreads();
    if (tid == 0) {
        int s = 0;
        for (int i = 0; i < 256; i++) { int t = cb[i]; cb[i] = s; s += t; }
        totb = s < 64 ? s : 64;
        s = 0;
        for (int i = 0; i < 256; i++) { int t = cc2[i]; cc2[i] = s; s += t; }
        totc = s < 64 ? s : 64;
    }
    __syncthreads();
    {
        int ob = cb[tid], oc = cc2[tid];
#pragma unroll
        for (int t = 0; t < 8; t++) {
            int v = v0 + t;
            if (v < VV) {
                if (br[v] != 0.f && ob < 64) { nzb[ob] = v; vb[ob] = br[v]; ob++; }
                if (cr[v] != 0.f && oc < 64) { nzc[oc] = v; vc[oc] = cr[v]; oc++; }
            }
        }
    }
    __syncthreads();
    int d = tid;
    float acc = btb[d] + btk[d];
    int tb = totb, tc = totc;
    for (int i = 0; i < tb; i++) acc += vb[i] * Wtb[(size_t)nzb[i] * DD + d];
    for (int i = 0; i < tc; i++) acc += vc[i] * Wtk[(size_t)nzc[i] * DD + d];
    rulesm[d] = acc;
    __syncthreads();
    float q = bq[d];
#pragma unroll 4
    for (int e = 0; e < 256; e++) q += rulesm[e] * Wq[(size_t)e * DD + d];
    g_Q[(size_t)r * DD + d] = q * 0.125f;
}

// ---------------- TF32 mma GEMM, N=K=256, z-batched K/V projections ----------------
__global__ void __launch_bounds__(256, 2)
k_gemmKV(const float* __restrict__ A,
         const float* __restrict__ Wk, const float* __restrict__ bk, float* __restrict__ Kx,
         const float* __restrict__ Wv, const float* __restrict__ bv, float* __restrict__ Vx) {
    const float* W = blockIdx.z ? Wv : Wk;
    const float* bias = blockIdx.z ? bv : bk;
    float* C = blockIdx.z ? Vx : Kx;
    __shared__ float As[32][136];
    __shared__ float Bs[32][136];
    __shared__ float bsm[128];
    const int tid = threadIdx.x;
    const int row0 = blockIdx.y * 128, col0 = blockIdx.x * 128;
    const int warp = tid >> 5, lane = tid & 31;
    const int g = lane >> 2, tig = lane & 3;
    const int wr = (warp & 3) * 32, wc = (warp >> 2) * 64;
    if (tid < 128) bsm[tid] = bias[col0 + tid];
    float d[2][8][4];
#pragma unroll
    for (int rt = 0; rt < 2; rt++)
#pragma unroll
        for (int nt = 0; nt < 8; nt++)
#pragma unroll
            for (int q = 0; q < 4; q++) d[rt][nt][q] = 0.f;
    for (int k0 = 0; k0 < 256; k0 += 32) {
#pragma unroll
        for (int t = 0; t < 4; t++) {
            int idx = (tid + t * 256) * 4;
            int r = idx >> 5, kk = idx & 31;
            float4 v = *(const float4*)(A + (size_t)(row0 + r) * 256 + k0 + kk);
            As[kk][r] = tf32f(v.x); As[kk + 1][r] = tf32f(v.y);
            As[kk + 2][r] = tf32f(v.z); As[kk + 3][r] = tf32f(v.w);
        }
#pragma unroll
        for (int t = 0; t < 4; t++) {
            int idx = (tid + t * 256) * 4;
            int rk = idx >> 7, cc = idx & 127;
            float4 v = *(const float4*)(W + (size_t)(k0 + rk) * 256 + col0 + cc);
            *(float4*)&Bs[rk][cc] = make_float4(tf32f(v.x), tf32f(v.y), tf32f(v.z), tf32f(v.w));
        }
        __syncthreads();
#pragma unroll
        for (int ks = 0; ks < 32; ks += 8) {
            unsigned a[2][4];
#pragma unroll
            for (int rt = 0; rt < 2; rt++) {
                int rb = wr + rt * 16 + g;
                a[rt][0] = __float_as_uint(As[ks + tig][rb]);
                a[rt][1] = __float_as_uint(As[ks + tig][rb + 8]);
                a[rt][2] = __float_as_uint(As[ks + tig + 4][rb]);
                a[rt][3] = __float_as_uint(As[ks + tig + 4][rb + 8]);
            }
#pragma unroll
            for (int nt = 0; nt < 8; nt++) {
                int nb = wc + nt * 8 + g;
                unsigned b0 = __float_as_uint(Bs[ks + tig][nb]);
                unsigned b1 = __float_as_uint(Bs[ks + tig + 4][nb]);
                mma8(d[0][nt], a[0], b0, b1);
                mma8(d[1][nt], a[1], b0, b1);
            }
        }
        __syncthreads();
    }
#pragma unroll
    for (int rt = 0; rt < 2; rt++) {
        int r = row0 + wr + rt * 16 + g;
#pragma unroll
        for (int nt = 0; nt < 8; nt++) {
            int ccol = wc + nt * 8 + tig * 2;
            float bv0 = bsm[ccol], bv1 = bsm[ccol + 1];
            float2 v0 = make_float2(d[rt][nt][0] + bv0, d[rt][nt][1] + bv1);
            float2 v1 = make_float2(d[rt][nt][2] + bv0, d[rt][nt][3] + bv1);
            *(float2*)(C + (size_t)r * 256 + col0 + ccol) = v0;
            *(float2*)(C + (size_t)(r + 8) * 256 + col0 + ccol) = v1;
        }
    }
}

// ---------------- TF32 mma cross-attention per (h, b) ----------------
// warp w owns rows w*32..w*32+31; smem: Qt/P union [64][264], Kt [64][72], Vs [64][72]
#define AQ_PITCH 264
#define AKV_PITCH 72
#define AT2_KT (64 * AQ_PITCH)
#define AT2_V (AT2_KT + 64 * AKV_PITCH)
#define ATTN_SMEM ((AT2_V + 64 * AKV_PITCH) * 4)
__global__ void __launch_bounds__(256, 2) k_attn() {
    extern __shared__ float sm[];
    float* QP = sm;            // Qt[k][r] then P[s][r]
    float* Kt = sm + AT2_KT;   // [k][s]
    float* Vs = sm + AT2_V;    // [s][d]
    const int tid = threadIdx.x;
    const int h = blockIdx.x, b = blockIdx.y;
    for (int idx = tid; idx < 256 * 64; idx += 256) {
        int k = idx & 63, r = idx >> 6;
        QP[k * AQ_PITCH + r] = tf32f(g_Q[(size_t)r * DD + h * 64 + k]);
    }
    for (int idx = tid; idx < 64 * 64; idx += 256) {
        int k = idx & 63, s = idx >> 6;
        Kt[k * AKV_PITCH + s] = tf32f(g_Kx[(size_t)(b * SS + s) * DD + h * 64 + k]);
        Vs[s * AKV_PITCH + k] = tf32f(g_Vx[(size_t)(b * SS + s) * DD + h * 64 + k]);
    }
    __syncthreads();
    const int warp = tid >> 5, lane = tid & 31;
    const int g = lane >> 2, tig = lane & 3;
    const int wr = warp * 32;
    float d[2][8][4];
#pragma unroll
    for (int rt = 0; rt < 2; rt++)
#pragma unroll
        for (int nt = 0; nt < 8; nt++)
#pragma unroll
            for (int q = 0; q < 4; q++) d[rt][nt][q] = 0.f;
    // phase 1: S = Q @ K^T
#pragma unroll
    for (int ks = 0; ks < 64; ks += 8) {
        unsigned a[2][4];
#pragma unroll
        for (int rt = 0; rt < 2; rt++) {
            int rb = wr + rt * 16 + g;
            a[rt][0] = __float_as_uint(QP[(ks + tig) * AQ_PITCH + rb]);
            a[rt][1] = __float_as_uint(QP[(ks + tig) * AQ_PITCH + rb + 8]);
            a[rt][2] = __float_as_uint(QP[(ks + tig + 4) * AQ_PITCH + rb]);
            a[rt][3] = __float_as_uint(QP[(ks + tig + 4) * AQ_PITCH + rb + 8]);
        }
#pragma unroll
        for (int nt = 0; nt < 8; nt++) {
            int nb = nt * 8 + g;
            unsigned b0 = __float_as_uint(Kt[(ks + tig) * AKV_PITCH + nb]);
            unsigned b1 = __float_as_uint(Kt[(ks + tig + 4) * AKV_PITCH + nb]);
            mma8(d[0][nt], a[0], b0, b1);
            mma8(d[1][nt], a[1], b0, b1);
        }
    }
    // softmax: each thread holds 2 rows per rt (r0, r0+8), cols nt*8+tig*2(+1);
    // row is shared among the 4 consecutive lanes with same g -> shfl_xor 1,2
#pragma unroll
    for (int rt = 0; rt < 2; rt++) {
        float mA = -1e30f, mB = -1e30f;
#pragma unroll
        for (int nt = 0; nt < 8; nt++) {
            mA = fmaxf(mA, fmaxf(d[rt][nt][0], d[rt][nt][1]));
            mB = fmaxf(mB, fmaxf(d[rt][nt][2], d[rt][nt][3]));
        }
        mA = fmaxf(mA, __shfl_xor_sync(0xffffffffu, mA, 1));
        mA = fmaxf(mA, __shfl_xor_sync(0xffffffffu, mA, 2));
        mB = fmaxf(mB, __shfl_xor_sync(0xffffffffu, mB, 1));
        mB = fmaxf(mB, __shfl_xor_sync(0xffffffffu, mB, 2));
        float sA = 0.f, sB = 0.f;
#pragma unroll
        for (int nt = 0; nt < 8; nt++) {
            d[rt][nt][0] = __expf(d[rt][nt][0] - mA);
            d[rt][nt][1] = __expf(d[rt][nt][1] - mA);
            d[rt][nt][2] = __expf(d[rt][nt][2] - mB);
            d[rt][nt][3] = __expf(d[rt][nt][3] - mB);
            sA += d[rt][nt][0] + d[rt][nt][1];
            sB += d[rt][nt][2] + d[rt][nt][3];
        }
        sA += __shfl_xor_sync(0xffffffffu, sA, 1);
        sA += __shfl_xor_sync(0xffffffffu, sA, 2);
        sB += __shfl_xor_sync(0xffffffffu, sB, 1);
        sB += __shfl_xor_sync(0xffffffffu, sB, 2);
        float iA = 1.f / sA, iB = 1.f / sB;
#pragma unroll
        for (int nt = 0; nt < 8; nt++) {
            d[rt][nt][0] *= iA; d[rt][nt][1] *= iA;
            d[rt][nt][2] *= iB; d[rt][nt][3] *= iB;
        }
    }
    __syncthreads();   // all Qt reads complete; QP becomes P[s][r]
#pragma unroll
    for (int rt = 0; rt < 2; rt++) {
        int r0 = wr + rt * 16 + g;
#pragma unroll
        for (int nt = 0; nt < 8; nt++) {
            int s0 = nt * 8 + tig * 2;
            QP[s0 * AQ_PITCH + r0] = tf32f(d[rt][nt][0]);
            QP[(s0 + 1) * AQ_PITCH + r0] = tf32f(d[rt][nt][1]);
            QP[s0 * AQ_PITCH + r0 + 8] = tf32f(d[rt][nt][2]);
            QP[(s0 + 1) * AQ_PITCH + r0 + 8] = tf32f(d[rt][nt][3]);
        }
    }
    __syncthreads();
    // phase 2: ctx = P @ V
#pragma unroll
    for (int rt = 0; rt < 2; rt++)
#pragma unroll
        for (int nt = 0; nt < 8; nt++)
#pragma unroll
            for (int q = 0; q < 4; q++) d[rt][nt][q] = 0.f;
#pragma unroll
    for (int ss = 0; ss < 64; ss += 8) {
        unsigned a[2][4];
#pragma unroll
        for (int rt = 0; rt < 2; rt++) {
            int rb = wr + rt * 16 + g;
            a[rt][0] = __float_as_uint(QP[(ss + tig) * AQ_PITCH + rb]);
            a[rt][1] = __float_as_uint(QP[(ss + tig) * AQ_PITCH + rb + 8]);
            a[rt][2] = __float_as_uint(QP[(ss + tig + 4) * AQ_PITCH + rb]);
            a[rt][3] = __float_as_uint(QP[(ss + tig + 4) * AQ_PITCH + rb + 8]);
        }
#pragma unroll
        for (int nt = 0; nt < 8; nt++) {
            int nb = nt * 8 + g;
            unsigned b0 = __float_as_uint(Vs[(ss + tig) * AKV_PITCH + nb]);
            unsigned b1 = __float_as_uint(Vs[(ss + tig + 4) * AKV_PITCH + nb]);
            mma8(d[0][nt], a[0], b0, b1);
            mma8(d[1][nt], a[1], b0, b1);
        }
    }
#pragma unroll
    for (int rt = 0; rt < 2; rt++) {
        int r = wr + rt * 16 + g;
#pragma unroll
        for (int nt = 0; nt < 8; nt++) {
            int ccol = h * 64 + nt * 8 + tig * 2;
            *(float2*)(g_ctx + (size_t)(b * RR + r) * DD + ccol) =
                make_float2(d[rt][nt][0], d[rt][nt][1]);
            *(float2*)(g_ctx + (size_t)(b * RR + r + 8) * DD + ccol) =
                make_float2(d[rt][nt][2], d[rt][nt][3]);
        }
    }
}

// ---------------- gathered per-class GEMM (TF32 mma) ----------------
__global__ void __launch_bounds__(256, 2)
k_hw1g() {
    const int c = blockIdx.y;
    const int cnt = g_memb_cnt[c];
    const int Mc = BB * cnt;
    const int row0 = blockIdx.x * 128;
    if (row0 >= Mc) return;
    __shared__ float As[32][136];
    __shared__ float Bs[32][136];
    __shared__ float bsm[128];
    __shared__ int rowbase[128];
    __shared__ int outbase[128];
    const int tid = threadIdx.x;
    const int warp = tid >> 5, lane = tid & 31;
    const int g = lane >> 2, tig = lane & 3;
    const int wr = (warp & 3) * 32, wc = (warp >> 2) * 64;
    if (tid < 128) {
        bsm[tid] = g_bo1[c * 128 + tid];
        int gg = row0 + tid;
        if (gg < Mc) {
            int b = gg / cnt, mr = gg - b * cnt;
            int ridx = g_memb_idx[c * MAXRC + mr];
            rowbase[tid] = (b * RR + ridx) * DD;
            outbase[tid] = ((c * BB + b) * MAXRC + mr) * 128;
        } else { rowbase[tid] = 0; outbase[tid] = -1; }
    }
    __syncthreads();
    const float* Wc = g_Wf + (size_t)c * DD * 128;
    float d[2][8][4];
#pragma unroll
    for (int rt = 0; rt < 2; rt++)
#pragma unroll
        for (int nt = 0; nt < 8; nt++)
#pragma unroll
            for (int q = 0; q < 4; q++) d[rt][nt][q] = 0.f;
    for (int k0 = 0; k0 < 256; k0 += 32) {
#pragma unroll
        for (int t = 0; t < 4; t++) {
            int idx = (tid + t * 256) * 4;
            int r = idx >> 5, kk = idx & 31;
            float4 v = *(const float4*)(g_ctx + (size_t)rowbase[r] + k0 + kk);
            As[kk][r] = tf32f(v.x); As[kk + 1][r] = tf32f(v.y);
            As[kk + 2][r] = tf32f(v.z); As[kk + 3][r] = tf32f(v.w);
        }
#pragma unroll
        for (int t = 0; t < 4; t++) {
            int idx = (tid + t * 256) * 4;
            int rk = idx >> 7, cc = idx & 127;
            float4 v = *(const float4*)(Wc + (size_t)(k0 + rk) * 128 + cc);
            *(float4*)&Bs[rk][cc] = make_float4(tf32f(v.x), tf32f(v.y), tf32f(v.z), tf32f(v.w));
        }
        __syncthreads();
#pragma unroll
        for (int ks = 0; ks < 32; ks += 8) {
            unsigned a[2][4];
#pragma unroll
            for (int rt = 0; rt < 2; rt++) {
                int rb = wr + rt * 16 + g;
                a[rt][0] = __float_as_uint(As[ks + tig][rb]);
                a[rt][1] = __float_as_uint(As[ks + tig][rb + 8]);
                a[rt][2] = __float_as_uint(As[ks + tig + 4][rb]);
                a[rt][3] = __float_as_uint(As[ks + tig + 4][rb + 8]);
            }
#pragma unroll
            for (int nt = 0; nt < 8; nt++) {
                int nb = wc + nt * 8 + g;
                unsigned b0 = __float_as_uint(Bs[ks + tig][nb]);
                unsigned b1 = __float_as_uint(Bs[ks + tig + 4][nb]);
                mma8(d[0][nt], a[0], b0, b1);
                mma8(d[1][nt], a[1], b0, b1);
            }
        }
        __syncthreads();
    }
#pragma unroll
    for (int rt = 0; rt < 2; rt++) {
        int lr = wr + rt * 16 + g;
        int ob0 = outbase[lr], ob1 = outbase[lr + 8];
#pragma unroll
        for (int nt = 0; nt < 8; nt++) {
            int ccol = wc + nt * 8 + tig * 2;
            float bv0 = bsm[ccol], bv1 = bsm[ccol + 1];
            if (ob0 >= 0)
                *(float2*)(g_hW1c + (size_t)ob0 + ccol) =
                    make_float2(d[rt][nt][0] + bv0, d[rt][nt][1] + bv1);
            if (ob1 >= 0)
                *(float2*)(g_hW1c + (size_t)ob1 + ccol) =
                    make_float2(d[rt][nt][2] + bv0, d[rt][nt][3] + bv1);
        }
    }
}

// ---------------- Wf[c] = Wo @ W1[c]  (fp32, unchanged) ----------------
__global__ void __launch_bounds__(256, 2)
k_fusew(const float* __restrict__ Wo, const float* __restrict__ W1) {
    const int c = blockIdx.y;
    const int row0 = blockIdx.x * 128;
    __shared__ float As[32][130];
    __shared__ float Bs[32][128];
    const int tid = threadIdx.x;
    const float* Wc = W1 + (size_t)c * DD * 128;
    const int trow = tid >> 4, tcol = tid & 15;
    ull acc[4][8];
#pragma unroll
    for (int p = 0; p < 4; p++)
#pragma unroll
        for (int j = 0; j < 8; j++) acc[p][j] = 0ull;
    for (int k0 = 0; k0 < 256; k0 += 32) {
#pragma unroll
        for (int t = 0; t < 4; t++) {
            int idx = (tid + t * 256) * 4;
            int r = idx >> 5, kk = idx & 31;
            float4 v = *(const float4*)(Wo + (size_t)(row0 + r) * 256 + k0 + kk);
            As[kk][r] = v.x; As[kk + 1][r] = v.y; As[kk + 2][r] = v.z; As[kk + 3][r] = v.w;
        }
#pragma unroll
        for (int t = 0; t < 4; t++) {
            int idx = (tid + t * 256) * 4;
            int rk = idx >> 7, cc = idx & 127;
            *(float4*)&Bs[rk][cc] = *(const float4*)(Wc + (size_t)(k0 + rk) * 128 + cc);
        }
        __syncthreads();
#pragma unroll
        for (int k = 0; k < 32; k++) {
            ull a2[4], b2[8];
#pragma unroll
            for (int p = 0; p < 4; p++) a2[p] = *(const ull*)&As[k][trow * 8 + 2 * p];
#pragma unroll
            for (int j = 0; j < 8; j++) b2[j] = pkdup(Bs[k][tcol + 16 * j]);
#pragma unroll
            for (int p = 0; p < 4; p++)
#pragma unroll
                for (int j = 0; j < 8; j++) fma2(acc[p][j], a2[p], b2[j]);
        }
        __syncthreads();
    }
    float* Cc = g_Wf + (size_t)c * DD * 128;
#pragma unroll
    for (int p = 0; p < 4; p++) {
        float* C0 = Cc + (size_t)(row0 + trow * 8 + 2 * p) * 128;
        float* C1 = C0 + 128;
#pragma unroll
        for (int j = 0; j < 8; j++) {
            float lo, hi;
            unpk(acc[p][j], lo, hi);
            int cc = tcol + 16 * j;
            C0[cc] = lo;
            C1[cc] = hi;
        }
    }
}

// ---------------- fused prep: y==0 -> a2 projections; y==1 -> bo1 ----------------
__global__ void k_prep(const float* __restrict__ W2, const float* __restrict__ a2d,
                       const float* __restrict__ a2s, const float* __restrict__ bo,
                       const float* __restrict__ W1) {
    int c = blockIdx.x, f = threadIdx.x;
    if (blockIdx.y == 0) {
        float dv = 0.f, sv = 0.f;
        const float* wr = W2 + ((size_t)c * 128 + f) * 64;
#pragma unroll
        for (int g = 0; g < 64; g++) {
            float w = wr[g];
            dv += w * a2d[c * 64 + g];
            sv += w * a2s[c * 64 + g];
        }
        g_a2dp[c * 128 + f] = dv;
        g_a2sp[c * 128 + f] = sv;
    } else {
        const float* Wc = W1 + (size_t)c * DD * 128;
        float acc = 0.f;
        for (int e = 0; e < DD; e++) acc += bo[e] * Wc[(size_t)e * 128 + f];
        g_bo1[c * 128 + f] = acc;
    }
}

// ---------------- fused GAT stack v5 (unchanged) ----------------
#define MG_HWS 0
#define MG_WBUF 6144
#define MG_UNION 10496
#define MG_A1D 12544
#define MG_A1S 12672
#define MG_B1 12800
#define MG_AD2 12928
#define MG_AS2 13056
#define MG_D1 13184
#define MG_S1 13440
#define MG_DEN1 13696
#define MG_D2 13952
#define MG_S2 14208
#define MG_DEN2 14464
#define MG_COEF 14720
#define MG_GSUM 14976
#define MG_GVEC 15104
#define MG_LOG 15168
#define MG_MCS 15176
#define MG_MIDX 15432
#define MG_ADJB 15496
#define MG_JCS8 17800
#define MEGA_SMEM (18824 * 4)
__global__ void __launch_bounds__(512, 3)
k_mega(const float* __restrict__ a1s, const float* __restrict__ a1d,
       const float* __restrict__ b1, const float* __restrict__ W2,
       const float* __restrict__ b2, const float* __restrict__ Wl,
       const float* __restrict__ bl, float* __restrict__ out) {
    extern __shared__ float sm[];
    float* hws = sm + MG_HWS;
    float* wbufd = sm + MG_WBUF;
    float* denp = sm + MG_UNION;
    float* gpart = sm + MG_UNION;
    float* a1dv = sm + MG_A1D;
    float* a1sv = sm + MG_A1S;
    float* b1v = sm + MG_B1;
    float* ad2 = sm + MG_AD2;
    float* as2 = sm + MG_AS2;
    float* d1s = sm + MG_D1;
    float* s1s = sm + MG_S1;
    float* den1 = sm + MG_DEN1;
    float* d2s = sm + MG_D2;
    float* s2s = sm + MG_S2;
    float* den2 = sm + MG_DEN2;
    float* coef = sm + MG_COEF;
    float* gsum = sm + MG_GSUM;
    float* gvec = sm + MG_GVEC;
    float* logits = sm + MG_LOG;
    int* mcs = (int*)(sm + MG_MCS);
    int* midx = (int*)(sm + MG_MIDX);
    unsigned int* adjb = (unsigned int*)(sm + MG_ADJB);
    unsigned char* jcs8 = (unsigned char*)(sm + MG_JCS8);
    const int b = blockIdx.x, c = blockIdx.y, tid = threadIdx.x;
    const int warp = tid >> 5, lane = tid & 31;
    const int cnt = g_memb_cnt[c];
    const size_t base = (size_t)(c * BB + b);
    {
        const float4* src4 = (const float4*)(g_hW1c + base * MAXRC * 128);
        float4* dst4 = (float4*)hws;
        int n4 = cnt * 32;
        for (int i = tid; i < n4; i += 512) dst4[i] = src4[i];
    }
    {
        unsigned int* j32 = (unsigned int*)jcs8;
        const unsigned int* gsrc = (const unsigned int*)g_mn_jc8 + c * RR * MNCAP / 4;
        for (int i = tid; i < RR * MNCAP / 4; i += 512) j32[i] = gsrc[i];
    }
    if (tid < 128) {
        a1dv[tid] = a1d[c * 128 + tid];
        a1sv[tid] = a1s[c * 128 + tid];
        b1v[tid] = b1[c * 128 + tid];
        ad2[tid] = g_a2dp[c * 128 + tid];
        as2[tid] = g_a2sp[c * 128 + tid];
    }
    if (tid < 256) {
        d1s[tid] = 0.f; s1s[tid] = 0.f;
        mcs[tid] = g_mn_cnt[c * RR + tid];
#pragma unroll
        for (int w = 0; w < 8; w++) adjb[tid * 9 + w] = g_adjbits[tid * 8 + w];
    }
    if (tid < MAXRC) midx[tid] = g_memb_idx[c * MAXRC + tid];
    __syncthreads();
    for (int mr = warp; mr < cnt; mr += 16) {
        const float4* hp = (const float4*)(hws + mr * HW_PITCH);
        float4 x = hp[lane];
        float4 ad = ((const float4*)a1dv)[lane];
        float4 as = ((const float4*)a1sv)[lane];
        float dv = x.x * ad.x + x.y * ad.y + x.z * ad.z + x.w * ad.w;
        float sv = x.x * as.x + x.y * as.y + x.z * as.z + x.w * as.w;
#pragma unroll
        for (int o = 16; o > 0; o >>= 1) {
            dv += __shfl_xor_sync(0xffffffffu, dv, o);
            sv += __shfl_xor_sync(0xffffffffu, sv, o);
        }
        if (lane == 0) { int ridx = midx[mr]; d1s[ridx] = dv; s1s[ridx] = sv; }
    }
    __syncthreads();
    {
        int half = tid >> 8, i = tid & 255;
        float di = d1s[i];
        float dsum = 0.f;
#pragma unroll
        for (int w = half * 4; w < half * 4 + 4; w++) {
            unsigned int bits = adjb[i * 9 + w];
            while (bits) {
                int t = __ffs(bits) - 1;
                bits &= bits - 1;
                dsum += __expf(lrelu02(di + s1s[w * 32 + t]));
            }
        }
        denp[tid] = dsum;
    }
    __syncthreads();
    if (tid < 256) {
        float inv = 1.f / (denp[tid] + denp[tid + 256]);
        int mc = mcs[tid];
        float di = d1s[tid];
        const unsigned char* jr = jcs8 + tid * 16;
        for (int m = 0; m < mc; m++)
            wbufd[tid * 17 + m] = __expf(lrelu02(di + s1s[midx[jr[m]]])) * inv;
    }
    __syncthreads();
    {
        float4 bb = ((const float4*)b1v)[lane];
        float4 ad = ((const float4*)ad2)[lane];
        float4 as = ((const float4*)as2)[lane];
#pragma unroll 4
        for (int it = 0; it < 16; it++) {
            int i = it * 16 + warp;
            int mc = mcs[i];
            float4 h;
            if (mc == 0) {
                h.x = fmaxf(bb.x, 0.f); h.y = fmaxf(bb.y, 0.f);
                h.z = fmaxf(bb.z, 0.f); h.w = fmaxf(bb.w, 0.f);
            } else {
                const float* wd = wbufd + i * 17;
                const unsigned char* jr = jcs8 + i * 16;
                float4 acc = make_float4(0.f, 0.f, 0.f, 0.f);
                for (int m = 0; m < mc; m++) {
                    float w = wd[m];
                    float4 hv = *(const float4*)(hws + (int)jr[m] * HW_PITCH + 4 * lane);
                    acc.x += w * hv.x; acc.y += w * hv.y;
                    acc.z += w * hv.z; acc.w += w * hv.w;
                }
                h.x = fmaxf(acc.x + bb.x, 0.f); h.y = fmaxf(acc.y + bb.y, 0.f);
                h.z = fmaxf(acc.z + bb.z, 0.f); h.w = fmaxf(acc.w + bb.w, 0.f);
            }
            float dv = h.x * ad.x + h.y * ad.y + h.z * ad.z + h.w * ad.w;
            float sv = h.x * as.x + h.y * as.y + h.z * as.z + h.w * as.w;
#pragma unroll
            for (int o = 16; o > 0; o >>= 1) {
                dv += __shfl_xor_sync(0xffffffffu, dv, o);
                sv += __shfl_xor_sync(0xffffffffu, sv, o);
            }
            if (lane == 0) { d2s[i] = dv; s2s[i] = sv; }
        }
    }
    __syncthreads();
    {
        int half = tid >> 8, i = tid & 255;
        float di = d2s[i];
        float dsum = 0.f;
#pragma unroll
        for (int w = half * 4; w < half * 4 + 4; w++) {
            unsigned int bits = adjb[i * 9 + w];
            while (bits) {
                int t = __ffs(bits) - 1;
                bits &= bits - 1;
                dsum += __expf(lrelu02(di + s2s[w * 32 + t]));
            }
        }
        denp[tid] = dsum;
    }
    __syncthreads();
    if (tid < 256) den2[tid] = 1.f / (denp[tid] + denp[tid + 256]);
    __syncthreads();
    {
        int half = tid >> 8, j = tid & 255;
        float sj = s2s[j];
        float cs = 0.f;
#pragma unroll
        for (int w = half * 4; w < half * 4 + 4; w++) {
            unsigned int bits = adjb[j * 9 + w];
            while (bits) {
                int t = __ffs(bits) - 1;
                bits &= bits - 1;
                int i2 = w * 32 + t;
                cs += __expf(lrelu02(d2s[i2] + sj)) * den2[i2];
            }
        }
        denp[tid] = cs;
    }
    __syncthreads();
    if (tid < 256) coef[tid] = denp[tid] + denp[tid + 256];
    __syncthreads();
    {
        float4 bb = ((const float4*)b1v)[lane];
        float4 p = make_float4(0.f, 0.f, 0.f, 0.f);
#pragma unroll 4
        for (int it = 0; it < 16; it++) {
            int i = it * 16 + warp;
            int mc = mcs[i];
            float cf = coef[i];
            float4 h;
            if (mc == 0) {
                h.x = fmaxf(bb.x, 0.f); h.y = fmaxf(bb.y, 0.f);
                h.z = fmaxf(bb.z, 0.f); h.w = fmaxf(bb.w, 0.f);
            } else {
                const float* wd = wbufd + i * 17;
                const unsigned char* jr = jcs8 + i * 16;
                float4 acc = make_float4(0.f, 0.f, 0.f, 0.f);
                for (int m = 0; m < mc; m++) {
                    float w = wd[m];
                    float4 hv = *(const float4*)(hws + (int)jr[m] * HW_PITCH + 4 * lane);
                    acc.x += w * hv.x; acc.y += w * hv.y;
                    acc.z += w * hv.z; acc.w += w * hv.w;
                }
                h.x = fmaxf(acc.x + bb.x, 0.f); h.y = fmaxf(acc.y + bb.y, 0.f);
                h.z = fmaxf(acc.z + bb.z, 0.f); h.w = fmaxf(acc.w + bb.w, 0.f);
            }
            p.x += cf * h.x; p.y += cf * h.y; p.z += cf * h.z; p.w += cf * h.w;
        }
        __syncthreads();
        ((float4*)(gpart + warp * 128))[lane] = p;
    }
    __syncthreads();
    if (tid < 128) {
        float s = 0.f;
#pragma unroll
        for (int w = 0; w < 16; w++) s += gpart[w * 128 + tid];
        gsum[tid] = s;
    }
    __syncthreads();
    if (tid < 64) {
        float acc = 0.f;
        for (int f = 0; f < 128; f++) acc += gsum[f] * W2[((size_t)c * 128 + f) * 64 + tid];
        gvec[tid] = acc + 256.f * b2[c * 64 + tid];
    }
    __syncthreads();
    if (tid < KKC) {
        float l = 0.f;
        for (int t = 0; t < 64; t++) l += gvec[t] * Wl[(c * 64 + t) * KKC + tid];
        logits[tid] = l + 256.f * bl[c * KKC + tid];
    }
    __syncthreads();
    if (tid == 0) {
        float mx = logits[0];
#pragma unroll
        for (int k = 1; k < KKC; k++) mx = fmaxf(mx, logits[k]);
        float se = 0.f;
#pragma unroll
        for (int k = 0; k < KKC; k++) se += __expf(logits[k] - mx);
        float lse = logf(se) + mx;
#pragma unroll
        for (int k = 0; k < KKC; k++) out[base * KKC + k] = logits[k] - lse;
    }
}

// ---------------- launcher ----------------
extern "C" void kernel_launch(void* const* d_in, const int* in_sizes, int n_in,
                              void* d_out, int out_size) {
    const float* vis = (const float*)d_in[0];
    const float* basic = (const float*)d_in[1];
    const float* crucial = (const float*)d_in[2];
    const float* Wtb = (const float*)d_in[3];
    const float* btb = (const float*)d_in[4];
    const float* Wtk = (const float*)d_in[5];
    const float* btk = (const float*)d_in[6];
    const float* Wq = (const float*)d_in[7];
    const float* bq = (const float*)d_in[8];
    const float* Wk = (const float*)d_in[9];
    const float* bk = (const float*)d_in[10];
    const float* Wv = (const float*)d_in[11];
    const float* bv = (const float*)d_in[12];
    const float* Wo = (const float*)d_in[13];
    const float* bo = (const float*)d_in[14];
    const float* W1 = (const float*)d_in[15];
    const float* a1s = (const float*)d_in[16];
    const float* a1d = (const float*)d_in[17];
    const float* b1 = (const float*)d_in[18];
    const float* W2 = (const float*)d_in[19];
    const float* a2s = (const float*)d_in[20];
    const float* a2d = (const float*)d_in[21];
    const float* b2 = (const float*)d_in[22];
    const float* Wl = (const float*)d_in[23];
    const float* bl = (const float*)d_in[24];
    const void* adjraw = d_in[25];
    const int* mask = (const int*)d_in[26];
    float* out = (float*)d_out;

    void *p_Kx, *p_Vx;
    cudaGetSymbolAddress(&p_Kx, g_Kx);
    cudaGetSymbolAddress(&p_Vx, g_Vx);

    cudaFuncSetAttribute((const void*)k_attn, cudaFuncAttributeMaxDynamicSharedMemorySize, ATTN_SMEM);
    cudaFuncSetAttribute((const void*)k_mega, cudaFuncAttributeMaxDynamicSharedMemorySize, MEGA_SMEM);

    // profiled slot (#4) = k_attn (TF32 mma version)
    k_rule<<<RR, 256>>>(basic, crucial, Wtb, btb, Wtk, btk, Wq, bq);
    k_gemmKV<<<dim3(2, 128, 2), 256>>>(vis, Wk, bk, (float*)p_Kx, Wv, bv, (float*)p_Vx);
    k_sniff<<<1, 256>>>(adjraw);
    k_attn<<<dim3(4, BB), 256, ATTN_SMEM>>>();
    k_csr<<<RR, 256>>>(adjraw);
    k_memb<<<CC, 256>>>(mask);
    k_prep<<<dim3(CC, 2), 128>>>(W2, a2d, a2s, bo, W1);
    k_fusew<<<dim3(2, CC), 256>>>(Wo, W1);
    k_hw1g<<<dim3(96, CC), 256>>>();
    k_mega<<<dim3(BB, CC), 512, MEGA_SMEM>>>(a1s, a1d, b1, W2, b2, Wl, bl, out);
}